// round 1
// baseline (speedup 1.0000x reference)
#include <cuda_runtime.h>
#include <math.h>

#define B_  8
#define T_  2048
#define C_  512
#define H_  2
#define HS_ 256
#define BT_ (B_ * T_)
#define EPS_ 1e-5f

// ---------------- device scratch (static, allocation-free) ----------------
__device__ float g_h[BT_ * C_];                      // LN output / reused as attn-out
__device__ float g_q[BT_ * C_];                      // [B,T,H*HS]
__device__ float g_k[BT_ * C_];
__device__ float g_v[BT_ * C_];
__device__ float g_att[(size_t)B_ * H_ * T_ * T_];   // 268 MB attention scores
__device__ float g_x1[BT_ * C_];                     // residual after attention
__device__ float g_f1[BT_ * 4 * C_];                 // FFN intermediate
__device__ float g_wp[3 * C_ * C_];                  // packed Wq|Wk|Wv

// ---------------- weight repack: [H,C,HS] -> [C, H*HS] ----------------
__global__ void repack_kernel(const float* __restrict__ Wq,
                              const float* __restrict__ Wk,
                              const float* __restrict__ Wv) {
    int i = blockIdx.x * blockDim.x + threadIdx.x;
    if (i >= C_ * C_) return;
    int c = i / C_, j = i % C_;
    int h = j / HS_, d = j % HS_;
    int src = h * C_ * HS_ + c * HS_ + d;
    g_wp[i]               = Wq[src];
    g_wp[C_ * C_ + i]     = Wk[src];
    g_wp[2 * C_ * C_ + i] = Wv[src];
}

// ---------------- LayerNorm: one block per row of C=512 ----------------
__global__ void ln_kernel(const float* __restrict__ x, const float* __restrict__ g,
                          const float* __restrict__ b, float* __restrict__ out) {
    int row = blockIdx.x;
    int tid = threadIdx.x;  // 256 threads
    const float* xr = x + (size_t)row * C_;
    float v0 = xr[tid], v1 = xr[tid + 256];
    float s = v0 + v1, ss = v0 * v0 + v1 * v1;
#pragma unroll
    for (int o = 16; o; o >>= 1) {
        s  += __shfl_xor_sync(0xffffffffu, s, o);
        ss += __shfl_xor_sync(0xffffffffu, ss, o);
    }
    __shared__ float sh_s[8], sh_ss[8];
    if ((tid & 31) == 0) { sh_s[tid >> 5] = s; sh_ss[tid >> 5] = ss; }
    __syncthreads();
    s = 0.f; ss = 0.f;
#pragma unroll
    for (int i = 0; i < 8; i++) { s += sh_s[i]; ss += sh_ss[i]; }
    float mean = s * (1.0f / C_);
    float var  = ss * (1.0f / C_) - mean * mean;
    float inv  = rsqrtf(var + EPS_);
    float* orow = out + (size_t)row * C_;
    orow[tid]       = (v0 - mean) * inv * g[tid]       + b[tid];
    orow[tid + 256] = (v1 - mean) * inv * g[tid + 256] + b[tid + 256];
}

// ---------------- masked softmax over att rows (T=2048) ----------------
__global__ void softmax_kernel(const int* __restrict__ mask) {
    int r = blockIdx.x;             // (b*H + h)*T + t
    int t = r % T_;
    int b = (r / T_) / H_;
    float* row = g_att + (size_t)r * T_;
    const int* mrow = mask + (size_t)(b * T_ + t) * T_;
    int tid = threadIdx.x;          // 256 threads, 8 elems each
    float v[8];
    float mx = -1e30f;
#pragma unroll
    for (int i = 0; i < 8; i++) {
        int s = tid + i * 256;
        float a = row[s];
        if (mrow[s] == 0) a = -1e30f;
        v[i] = a;
        mx = fmaxf(mx, a);
    }
#pragma unroll
    for (int o = 16; o; o >>= 1) mx = fmaxf(mx, __shfl_xor_sync(0xffffffffu, mx, o));
    __shared__ float shm[8];
    if ((tid & 31) == 0) shm[tid >> 5] = mx;
    __syncthreads();
    mx = shm[0];
#pragma unroll
    for (int i = 1; i < 8; i++) mx = fmaxf(mx, shm[i]);
    float sum = 0.f;
#pragma unroll
    for (int i = 0; i < 8; i++) { v[i] = __expf(v[i] - mx); sum += v[i]; }
#pragma unroll
    for (int o = 16; o; o >>= 1) sum += __shfl_xor_sync(0xffffffffu, sum, o);
    __shared__ float shs[8];
    if ((tid & 31) == 0) shs[tid >> 5] = sum;
    __syncthreads();
    sum = 0.f;
#pragma unroll
    for (int i = 0; i < 8; i++) sum += shs[i];
    float inv = 1.0f / sum;
#pragma unroll
    for (int i = 0; i < 8; i++) row[tid + i * 256] = v[i] * inv;
}

// ---------------- tiled SGEMM, 128x128x8, 256 thr, TM=TN=8 ----------------
// MODE 0: C = alpha * A*B
// MODE 1: C = A*B + bias[n] + res[m*ldc+n]
// MODE 2: C = relu(A*B + bias[n])
// TRANSB: B is [N,K] row-major (dot of rows) — used for q*k^T
// Batched via blockIdx.z with two-level strides (z1 = z/bdiv, z2 = z%bdiv).
template <int MODE, bool TRANSB>
__global__ void __launch_bounds__(256, 2)
gemm_kernel(const float* __restrict__ A, const float* __restrict__ Bm,
            float* __restrict__ Cm,
            const float* __restrict__ bias, const float* __restrict__ res,
            int K, int lda, int ldb, int ldc,
            long long sA1, long long sA2, long long sB1, long long sB2,
            long long sC1, long long sC2, int bdiv, float alpha) {
    __shared__ float As[8][128];
    __shared__ float Bs[8][128];

    int z1 = blockIdx.z / bdiv, z2 = blockIdx.z % bdiv;
    A  += (size_t)z1 * sA1 + (size_t)z2 * sA2;
    Bm += (size_t)z1 * sB1 + (size_t)z2 * sB2;
    Cm += (size_t)z1 * sC1 + (size_t)z2 * sC2;

    const int m0 = blockIdx.y * 128, n0 = blockIdx.x * 128;
    const int tid = threadIdx.x;
    const int tx = tid & 15, ty = tid >> 4;
    const int arow = tid >> 1, ak = (tid & 1) << 2;   // A: 128 rows x 2 float4
    const int bk = tid >> 5, bn = (tid & 31) << 2;    // B NN: 8 rows x 32 float4

    float acc[8][8];
#pragma unroll
    for (int i = 0; i < 8; i++)
#pragma unroll
        for (int j = 0; j < 8; j++) acc[i][j] = 0.f;

    const float* Aptr = A + (size_t)(m0 + arow) * lda + ak;
    const float* Bptr = TRANSB ? (Bm + (size_t)(n0 + arow) * ldb + ak)
                               : (Bm + (size_t)bk * ldb + n0 + bn);

    for (int k0 = 0; k0 < K; k0 += 8) {
        float4 a4 = *(const float4*)(Aptr + k0);
        As[ak + 0][arow] = a4.x; As[ak + 1][arow] = a4.y;
        As[ak + 2][arow] = a4.z; As[ak + 3][arow] = a4.w;
        if (TRANSB) {
            float4 b4 = *(const float4*)(Bptr + k0);
            Bs[ak + 0][arow] = b4.x; Bs[ak + 1][arow] = b4.y;
            Bs[ak + 2][arow] = b4.z; Bs[ak + 3][arow] = b4.w;
        } else {
            float4 b4 = *(const float4*)(Bptr + (size_t)k0 * ldb);
            *(float4*)&Bs[bk][bn] = b4;
        }
        __syncthreads();
#pragma unroll
        for (int kk = 0; kk < 8; kk++) {
            float ra[8], rb[8];
            *(float4*)&ra[0] = *(const float4*)&As[kk][ty * 8];
            *(float4*)&ra[4] = *(const float4*)&As[kk][ty * 8 + 4];
            *(float4*)&rb[0] = *(const float4*)&Bs[kk][tx * 8];
            *(float4*)&rb[4] = *(const float4*)&Bs[kk][tx * 8 + 4];
#pragma unroll
            for (int i = 0; i < 8; i++)
#pragma unroll
                for (int j = 0; j < 8; j++) acc[i][j] += ra[i] * rb[j];
        }
        __syncthreads();
    }

    // epilogue
#pragma unroll
    for (int i = 0; i < 8; i++) {
        int m = m0 + ty * 8 + i;
        int nb = n0 + tx * 8;
        float* crow = Cm + (size_t)m * ldc + nb;
        const float* rrow = (MODE == 1) ? (res + (size_t)m * ldc + nb) : nullptr;
#pragma unroll
        for (int j = 0; j < 8; j += 4) {
            float4 o;
            float t0 = acc[i][j + 0], t1 = acc[i][j + 1], t2 = acc[i][j + 2], t3 = acc[i][j + 3];
            if (MODE == 0) {
                o.x = t0 * alpha; o.y = t1 * alpha; o.z = t2 * alpha; o.w = t3 * alpha;
            } else if (MODE == 1) {
                o.x = t0 + bias[nb + j + 0] + rrow[j + 0];
                o.y = t1 + bias[nb + j + 1] + rrow[j + 1];
                o.z = t2 + bias[nb + j + 2] + rrow[j + 2];
                o.w = t3 + bias[nb + j + 3] + rrow[j + 3];
            } else {
                o.x = fmaxf(t0 + bias[nb + j + 0], 0.f);
                o.y = fmaxf(t1 + bias[nb + j + 1], 0.f);
                o.z = fmaxf(t2 + bias[nb + j + 2], 0.f);
                o.w = fmaxf(t3 + bias[nb + j + 3], 0.f);
            }
            *(float4*)(crow + j) = o;
        }
    }
}

// ---------------- host launcher ----------------
extern "C" void kernel_launch(void* const* d_in, const int* in_sizes, int n_in,
                              void* d_out, int out_size) {
    const float* x     = (const float*)d_in[0];
    const int*   smask = (const int*)d_in[1];
    const float* Wq    = (const float*)d_in[2];
    const float* Wk    = (const float*)d_in[3];
    const float* Wv    = (const float*)d_in[4];
    const float* Wproj = (const float*)d_in[5];
    const float* bproj = (const float*)d_in[6];
    const float* W1    = (const float*)d_in[7];
    const float* b1    = (const float*)d_in[8];
    const float* W2    = (const float*)d_in[9];
    const float* b2    = (const float*)d_in[10];
    const float* g1    = (const float*)d_in[11];
    const float* be1   = (const float*)d_in[12];
    const float* g2    = (const float*)d_in[13];
    const float* be2   = (const float*)d_in[14];
    float* out = (float*)d_out;

    float *pH, *pQ, *pK, *pV, *pAtt, *pX1, *pF1, *pWp;
    cudaGetSymbolAddress((void**)&pH,   g_h);
    cudaGetSymbolAddress((void**)&pQ,   g_q);
    cudaGetSymbolAddress((void**)&pK,   g_k);
    cudaGetSymbolAddress((void**)&pV,   g_v);
    cudaGetSymbolAddress((void**)&pAtt, g_att);
    cudaGetSymbolAddress((void**)&pX1,  g_x1);
    cudaGetSymbolAddress((void**)&pF1,  g_f1);
    cudaGetSymbolAddress((void**)&pWp,  g_wp);

    // 1. pack per-head QKV weights -> [C, H*HS]
    repack_kernel<<<(C_ * C_ + 255) / 256, 256>>>(Wq, Wk, Wv);

    // 2. LN1
    ln_kernel<<<BT_, 256>>>(x, g1, be1, pH);

    // 3. QKV projections: [BT,C] x [C,C]
    dim3 gq(C_ / 128, BT_ / 128, 1);
    gemm_kernel<0, false><<<gq, 256>>>(pH, pWp,                pQ, nullptr, nullptr,
        C_, C_, C_, C_, 0, 0, 0, 0, 0, 0, 1, 1.0f);
    gemm_kernel<0, false><<<gq, 256>>>(pH, pWp + C_ * C_,      pK, nullptr, nullptr,
        C_, C_, C_, C_, 0, 0, 0, 0, 0, 0, 1, 1.0f);
    gemm_kernel<0, false><<<gq, 256>>>(pH, pWp + 2 * C_ * C_,  pV, nullptr, nullptr,
        C_, C_, C_, C_, 0, 0, 0, 0, 0, 0, 1, 1.0f);

    // 4. scores = scale * q k^T  (batched over b,h; NT GEMM)
    {
        dim3 g(T_ / 128, T_ / 128, B_ * H_);
        gemm_kernel<0, true><<<g, 256>>>(pQ, pK, pAtt, nullptr, nullptr,
            HS_, C_, C_, T_,
            (long long)T_ * C_, HS_,            // A strides (per b, per h)
            (long long)T_ * C_, HS_,            // B strides
            (long long)H_ * T_ * T_, (long long)T_ * T_,  // C strides
            H_, 0.0625f);                       // 1/sqrt(256)
    }

    // 5. masked softmax
    softmax_kernel<<<B_ * H_ * T_, 256>>>(smask);

    // 6. o = att @ v  -> concat-head layout in pH
    {
        dim3 g(HS_ / 128, T_ / 128, B_ * H_);
        gemm_kernel<0, false><<<g, 256>>>(pAtt, pV, pH, nullptr, nullptr,
            T_, T_, C_, C_,
            (long long)H_ * T_ * T_, (long long)T_ * T_,
            (long long)T_ * C_, HS_,
            (long long)T_ * C_, HS_,
            H_, 1.0f);
    }

    // 7. x1 = x + o @ Wproj + bproj
    gemm_kernel<1, false><<<dim3(C_ / 128, BT_ / 128, 1), 256>>>(pH, Wproj, pX1, bproj, x,
        C_, C_, C_, C_, 0, 0, 0, 0, 0, 0, 1, 1.0f);

    // 8. LN2 (reuse pH)
    ln_kernel<<<BT_, 256>>>(pX1, g2, be2, pH);

    // 9. f1 = relu(h2 @ W1 + b1)
    gemm_kernel<2, false><<<dim3(4 * C_ / 128, BT_ / 128, 1), 256>>>(pH, W1, pF1, b1, nullptr,
        C_, C_, 4 * C_, 4 * C_, 0, 0, 0, 0, 0, 0, 1, 1.0f);

    // 10. out = x1 + f1 @ W2 + b2
    gemm_kernel<1, false><<<dim3(C_ / 128, BT_ / 128, 1), 256>>>(pF1, W2, out, b2, pX1,
        4 * C_, 4 * C_, C_, C_, 0, 0, 0, 0, 0, 0, 1, 1.0f);
}

// round 3
// speedup vs baseline: 3.7917x; 3.7917x over previous
#include <cuda_runtime.h>
#include <cstdint>
#include <math.h>

#define B_  8
#define T_  2048
#define C_  512
#define H_  2
#define HS_ 256
#define BT_ (B_ * T_)
#define EPS_ 1e-5f

// ---------------- device scratch (static, allocation-free) ----------------
__device__ __align__(256) float g_h[BT_ * C_];                       // LN out / attn-out
__device__ __align__(256) float g_qkv[(size_t)BT_ * 3 * C_];         // [BT, 1536] q|k|v
__device__ __align__(256) float g_vT[(size_t)B_ * H_ * HS_ * T_];    // v transposed per (b,h)
__device__ __align__(256) float g_att[(size_t)B_ * H_ * T_ * T_];    // attention scores
__device__ __align__(256) float g_x1[BT_ * C_];                      // residual after attention
__device__ __align__(256) float g_f1[(size_t)BT_ * 4 * C_];          // FFN intermediate
__device__ __align__(256) float g_wqkvT[3 * C_ * C_];                // [1536, 512]
__device__ __align__(256) float g_wprojT[C_ * C_];                   // [512, 512]
__device__ __align__(256) float g_w1T[4 * C_ * C_];                  // [2048, 512]
__device__ __align__(256) float g_w2T[4 * C_ * C_];                  // [512, 2048]

// ---------------- small PTX helpers ----------------
__device__ __forceinline__ uint32_t su32(const void* p) {
    uint32_t a;
    asm("{ .reg .u64 t; cvta.to.shared.u64 t, %1; cvt.u32.u64 %0, t; }" : "=r"(a) : "l"(p));
    return a;
}
__device__ __forceinline__ float rtf32(float f) {   // round-to-nearest tf32
    uint32_t u;
    asm("cvt.rna.tf32.f32 %0, %1;" : "=r"(u) : "f"(f));
    return __uint_as_float(u);
}
__device__ __forceinline__ void cp16(uint32_t dst, const void* src) {
    asm volatile("cp.async.cg.shared.global [%0], [%1], 16;" :: "r"(dst), "l"(src));
}
__device__ __forceinline__ void mma_tf32(float* d, const uint32_t* a, const uint32_t* b) {
    asm volatile(
        "mma.sync.aligned.m16n8k8.row.col.f32.tf32.tf32.f32 "
        "{%0,%1,%2,%3}, {%4,%5,%6,%7}, {%8,%9}, {%0,%1,%2,%3};"
        : "+f"(d[0]), "+f"(d[1]), "+f"(d[2]), "+f"(d[3])
        : "r"(a[0]), "r"(a[1]), "r"(a[2]), "r"(a[3]), "r"(b[0]), "r"(b[1]));
}

// ---------------- weight repacks (transpose + tf32 round) ----------------
__global__ void repack_qkvT(const float* __restrict__ Wq, const float* __restrict__ Wk,
                            const float* __restrict__ Wv) {
    int idx = blockIdx.x * blockDim.x + threadIdx.x;     // [0, 1536*512)
    if (idx >= 3 * C_ * C_) return;
    int n = idx / C_, k = idx % C_;
    int part = n / C_;
    int nn = n % C_;
    int h = nn / HS_, d = nn % HS_;
    const float* W = (part == 0) ? Wq : ((part == 1) ? Wk : Wv);
    g_wqkvT[idx] = rtf32(W[(size_t)h * C_ * HS_ + (size_t)k * HS_ + d]);
}

// out[n*K+k] = in[k*N+n], tiled, rounded to tf32
__global__ void transpose_w(const float* __restrict__ in, float* __restrict__ out,
                            int K, int N) {
    __shared__ float t[32][33];
    int n0 = blockIdx.x * 32, k0 = blockIdx.y * 32;
    int tx = threadIdx.x, ty = threadIdx.y;  // 32x8
#pragma unroll
    for (int i = 0; i < 32; i += 8)
        t[ty + i][tx] = in[(size_t)(k0 + ty + i) * N + n0 + tx];
    __syncthreads();
#pragma unroll
    for (int i = 0; i < 32; i += 8)
        out[(size_t)(n0 + ty + i) * K + k0 + tx] = rtf32(t[tx][ty + i]);
}

// vT[(b*H+h)*HS + d][s] = qkv[b*T+s][1024 + h*256 + d]
__global__ void transpose_v(const float* __restrict__ qkv) {
    __shared__ float t[32][33];
    int z = blockIdx.z;
    int b = z / H_, h = z % H_;
    int s0 = blockIdx.x * 32, d0 = blockIdx.y * 32;
    int tx = threadIdx.x, ty = threadIdx.y;
    const float* in = qkv + (size_t)b * T_ * 1536 + 2 * C_ + h * HS_;
#pragma unroll
    for (int i = 0; i < 32; i += 8)
        t[ty + i][tx] = in[(size_t)(s0 + ty + i) * 1536 + d0 + tx];
    __syncthreads();
    float* out = g_vT + ((size_t)z * HS_ + d0) * T_ + s0;
#pragma unroll
    for (int i = 0; i < 32; i += 8)
        out[(size_t)(ty + i) * T_ + tx] = t[tx][ty + i];
}

// ---------------- LayerNorm: one block per row of C=512 (tf32-rounded out) ----------------
__global__ void ln_kernel(const float* __restrict__ x, const float* __restrict__ g,
                          const float* __restrict__ b, float* __restrict__ out) {
    int row = blockIdx.x;
    int tid = threadIdx.x;  // 256 threads
    const float* xr = x + (size_t)row * C_;
    float v0 = xr[tid], v1 = xr[tid + 256];
    float s = v0 + v1, ss = v0 * v0 + v1 * v1;
#pragma unroll
    for (int o = 16; o; o >>= 1) {
        s  += __shfl_xor_sync(0xffffffffu, s, o);
        ss += __shfl_xor_sync(0xffffffffu, ss, o);
    }
    __shared__ float sh_s[8], sh_ss[8];
    if ((tid & 31) == 0) { sh_s[tid >> 5] = s; sh_ss[tid >> 5] = ss; }
    __syncthreads();
    s = 0.f; ss = 0.f;
#pragma unroll
    for (int i = 0; i < 8; i++) { s += sh_s[i]; ss += sh_ss[i]; }
    float mean = s * (1.0f / C_);
    float var  = ss * (1.0f / C_) - mean * mean;
    float inv  = rsqrtf(var + EPS_);
    float* orow = out + (size_t)row * C_;
    orow[tid]       = rtf32((v0 - mean) * inv * g[tid]       + b[tid]);
    orow[tid + 256] = rtf32((v1 - mean) * inv * g[tid + 256] + b[tid + 256]);
}

// ---------------- masked softmax over att rows (T=2048), tf32-rounded out --------------
__global__ void softmax_kernel(const int* __restrict__ mask) {
    int r = blockIdx.x;             // (b*H + h)*T + t
    int t = r % T_;
    int b = (r / T_) / H_;
    float* row = g_att + (size_t)r * T_;
    const int* mrow = mask + (size_t)(b * T_ + t) * T_;
    int tid = threadIdx.x;          // 256 threads, 8 elems each
    float v[8];
    float mx = -1e30f;
#pragma unroll
    for (int i = 0; i < 8; i++) {
        int s = tid + i * 256;
        float a = row[s];
        if (mrow[s] == 0) a = -1e30f;
        v[i] = a;
        mx = fmaxf(mx, a);
    }
#pragma unroll
    for (int o = 16; o; o >>= 1) mx = fmaxf(mx, __shfl_xor_sync(0xffffffffu, mx, o));
    __shared__ float shm[8];
    if ((tid & 31) == 0) shm[tid >> 5] = mx;
    __syncthreads();
    mx = shm[0];
#pragma unroll
    for (int i = 1; i < 8; i++) mx = fmaxf(mx, shm[i]);
    float sum = 0.f;
#pragma unroll
    for (int i = 0; i < 8; i++) { v[i] = __expf(v[i] - mx); sum += v[i]; }
#pragma unroll
    for (int o = 16; o; o >>= 1) sum += __shfl_xor_sync(0xffffffffu, sum, o);
    __shared__ float shs[8];
    if ((tid & 31) == 0) shs[tid >> 5] = sum;
    __syncthreads();
    sum = 0.f;
#pragma unroll
    for (int i = 0; i < 8; i++) sum += shs[i];
    float inv = 1.0f / sum;
#pragma unroll
    for (int i = 0; i < 8; i++) row[tid + i * 256] = rtf32(v[i] * inv);
}

// ---------------- mma.sync tf32 NT GEMM: 128x128 block tile, K=32/stage -------------
// A [M,K] row-major (lda), B [N,K] row-major (ldb) -> C [M,N] (ldc). 4 warps,
// warp tile 64x64 (m16n8k8 fragments), 2-stage cp.async pipeline, 2 CTAs/SM.
// Smem rows padded to 36 floats: fragment-load banks = 4r+c (conflict-free).
// MODE 0: C = alpha * acc               (scores)
// MODE 1: C = acc + bias[n] + res[m,n]  (proj / FFN2)
// MODE 2: C = rtf32(relu(acc + bias))   (FFN1)
// MODE 3: C = rtf32(acc)                (QKV / AV)
#define SROW   36                        // floats per padded smem row
#define STAGEF (128 * SROW * 2)          // floats per stage (A tile + B tile)
#define SHMB   (2 * STAGEF * 4)          // bytes: 2 stages

template <int MODE>
__global__ void __launch_bounds__(128, 2)
mma_gemm(const float* __restrict__ A, const float* __restrict__ Bm, float* __restrict__ Cm,
         const float* __restrict__ bias, const float* __restrict__ res,
         int K, int lda, int ldb, int ldc,
         long long sA1, long long sA2, long long sB1, long long sB2,
         long long sC1, long long sC2, int bdiv, float alpha) {
    extern __shared__ float sm[];
    const int tid = threadIdx.x, lane = tid & 31, wid = tid >> 5;
    const int wm = wid >> 1, wn = wid & 1;

    const int z1 = blockIdx.z / bdiv, z2 = blockIdx.z % bdiv;
    A  += (size_t)z1 * sA1 + (size_t)z2 * sA2;
    Bm += (size_t)z1 * sB1 + (size_t)z2 * sB2;
    Cm += (size_t)z1 * sC1 + (size_t)z2 * sC2;
    const int m0 = blockIdx.y * 128, n0 = blockIdx.x * 128;

    float acc[4][8][4];
#pragma unroll
    for (int i = 0; i < 4; i++)
#pragma unroll
        for (int j = 0; j < 8; j++)
#pragma unroll
            for (int c = 0; c < 4; c++) acc[i][j][c] = 0.f;

    // gmem->smem chunk mapping: thread owns k4 = tid&7, rows (tid>>3) + 16*t
    const int lrow = tid >> 3, k4 = tid & 7;
    const uint32_t sbase = su32(sm);
    const uint32_t dA0 = sbase + (uint32_t)(lrow * SROW + k4 * 4) * 4u;
    const uint32_t dB0 = dA0 + (uint32_t)(128 * SROW) * 4u;
    const float* gA0 = A  + (size_t)(m0 + lrow) * lda + k4 * 4;
    const float* gB0 = Bm + (size_t)(n0 + lrow) * ldb + k4 * 4;
    const int nk = K >> 5;

    // fragment smem base pointers (float units)
    const float* fA0 = sm + (wm * 64 + (lane >> 2)) * SROW + (lane & 3);
    const float* fB0 = sm + 128 * SROW + (wn * 64 + (lane >> 2)) * SROW + (lane & 3);

    // prologue: stage 0
#pragma unroll
    for (int t = 0; t < 8; t++) {
        cp16(dA0 + (uint32_t)(16 * t * SROW) * 4u, gA0 + (size_t)(16 * t) * lda);
        cp16(dB0 + (uint32_t)(16 * t * SROW) * 4u, gB0 + (size_t)(16 * t) * ldb);
    }
    asm volatile("cp.async.commit_group;");

    for (int j = 0; j < nk; j++) {
        // issue stage j+1 into the other buffer (its consumers synced last iter)
        if (j + 1 < nk) {
            const uint32_t soff = (uint32_t)(((j + 1) & 1) * STAGEF) * 4u;
            const float* ga = gA0 + (j + 1) * 32;
            const float* gb = gB0 + (j + 1) * 32;
#pragma unroll
            for (int t = 0; t < 8; t++) {
                cp16(dA0 + soff + (uint32_t)(16 * t * SROW) * 4u, ga + (size_t)(16 * t) * lda);
                cp16(dB0 + soff + (uint32_t)(16 * t * SROW) * 4u, gb + (size_t)(16 * t) * ldb);
            }
        }
        asm volatile("cp.async.commit_group;");
        asm volatile("cp.async.wait_group 1;");       // stage j landed
        __syncthreads();

        const float* pA = fA0 + (j & 1) * STAGEF;
        const float* pB = fB0 + (j & 1) * STAGEF;
#pragma unroll
        for (int ks = 0; ks < 4; ks++) {
            uint32_t aF[4][4], bF[8][2];
#pragma unroll
            for (int mt = 0; mt < 4; mt++) {
                const float* p = pA + mt * (16 * SROW) + ks * 8;
                aF[mt][0] = __float_as_uint(p[0]);
                aF[mt][1] = __float_as_uint(p[8 * SROW]);
                aF[mt][2] = __float_as_uint(p[4]);
                aF[mt][3] = __float_as_uint(p[8 * SROW + 4]);
            }
#pragma unroll
            for (int nt = 0; nt < 8; nt++) {
                const float* p = pB + nt * (8 * SROW) + ks * 8;
                bF[nt][0] = __float_as_uint(p[0]);
                bF[nt][1] = __float_as_uint(p[4]);
            }
#pragma unroll
            for (int mt = 0; mt < 4; mt++)
#pragma unroll
                for (int nt = 0; nt < 8; nt++)
                    mma_tf32(acc[mt][nt], aF[mt], bF[nt]);
        }
        __syncthreads();   // before next iter overwrites the other buffer
    }

    // epilogue
    const int r = lane >> 2, cq = 2 * (lane & 3);
#pragma unroll
    for (int mt = 0; mt < 4; mt++) {
        const int row0 = m0 + wm * 64 + mt * 16 + r;
#pragma unroll
        for (int nt = 0; nt < 8; nt++) {
            const int col = n0 + wn * 64 + nt * 8 + cq;
            float v0 = acc[mt][nt][0], v1 = acc[mt][nt][1];
            float v2 = acc[mt][nt][2], v3 = acc[mt][nt][3];
            float2 o0, o1;
            if (MODE == 0) {
                o0.x = v0 * alpha; o0.y = v1 * alpha;
                o1.x = v2 * alpha; o1.y = v3 * alpha;
            } else if (MODE == 1) {
                float b0 = bias[col], b1 = bias[col + 1];
                const float* r0p = res + (size_t)row0 * ldc + col;
                const float* r1p = res + (size_t)(row0 + 8) * ldc + col;
                o0.x = v0 + b0 + r0p[0]; o0.y = v1 + b1 + r0p[1];
                o1.x = v2 + b0 + r1p[0]; o1.y = v3 + b1 + r1p[1];
            } else if (MODE == 2) {
                float b0 = bias[col], b1 = bias[col + 1];
                o0.x = rtf32(fmaxf(v0 + b0, 0.f)); o0.y = rtf32(fmaxf(v1 + b1, 0.f));
                o1.x = rtf32(fmaxf(v2 + b0, 0.f)); o1.y = rtf32(fmaxf(v3 + b1, 0.f));
            } else {
                o0.x = rtf32(v0); o0.y = rtf32(v1);
                o1.x = rtf32(v2); o1.y = rtf32(v3);
            }
            *(float2*)(Cm + (size_t)row0 * ldc + col) = o0;
            *(float2*)(Cm + (size_t)(row0 + 8) * ldc + col) = o1;
        }
    }
}

// ---------------- host launcher ----------------
extern "C" void kernel_launch(void* const* d_in, const int* in_sizes, int n_in,
                              void* d_out, int out_size) {
    const float* x     = (const float*)d_in[0];
    const int*   smask = (const int*)d_in[1];
    const float* Wq    = (const float*)d_in[2];
    const float* Wk    = (const float*)d_in[3];
    const float* Wv    = (const float*)d_in[4];
    const float* Wproj = (const float*)d_in[5];
    const float* bproj = (const float*)d_in[6];
    const float* W1    = (const float*)d_in[7];
    const float* b1    = (const float*)d_in[8];
    const float* W2    = (const float*)d_in[9];
    const float* b2    = (const float*)d_in[10];
    const float* g1    = (const float*)d_in[11];
    const float* be1   = (const float*)d_in[12];
    const float* g2    = (const float*)d_in[13];
    const float* be2   = (const float*)d_in[14];
    float* out = (float*)d_out;

    float *pH, *pQKV, *pVT, *pAtt, *pX1, *pF1, *pWqkvT, *pWprojT, *pW1T, *pW2T;
    cudaGetSymbolAddress((void**)&pH,      g_h);
    cudaGetSymbolAddress((void**)&pQKV,    g_qkv);
    cudaGetSymbolAddress((void**)&pVT,     g_vT);
    cudaGetSymbolAddress((void**)&pAtt,    g_att);
    cudaGetSymbolAddress((void**)&pX1,     g_x1);
    cudaGetSymbolAddress((void**)&pF1,     g_f1);
    cudaGetSymbolAddress((void**)&pWqkvT,  g_wqkvT);
    cudaGetSymbolAddress((void**)&pWprojT, g_wprojT);
    cudaGetSymbolAddress((void**)&pW1T,    g_w1T);
    cudaGetSymbolAddress((void**)&pW2T,    g_w2T);

    cudaFuncSetAttribute(mma_gemm<0>, cudaFuncAttributeMaxDynamicSharedMemorySize, SHMB);
    cudaFuncSetAttribute(mma_gemm<1>, cudaFuncAttributeMaxDynamicSharedMemorySize, SHMB);
    cudaFuncSetAttribute(mma_gemm<2>, cudaFuncAttributeMaxDynamicSharedMemorySize, SHMB);
    cudaFuncSetAttribute(mma_gemm<3>, cudaFuncAttributeMaxDynamicSharedMemorySize, SHMB);
    dim3 blk(128);

    // weight repacks (rounded to tf32)
    repack_qkvT<<<(3 * C_ * C_ + 255) / 256, 256>>>(Wq, Wk, Wv);
    transpose_w<<<dim3(C_ / 32, C_ / 32), dim3(32, 8)>>>(Wproj, pWprojT, C_, C_);
    transpose_w<<<dim3(4 * C_ / 32, C_ / 32), dim3(32, 8)>>>(W1, pW1T, C_, 4 * C_);
    transpose_w<<<dim3(C_ / 32, 4 * C_ / 32), dim3(32, 8)>>>(W2, pW2T, 4 * C_, C_);

    // LN1
    ln_kernel<<<BT_, 256>>>(x, g1, be1, pH);

    // QKV fused: [BT,512] x [1536,512]^T -> [BT,1536]
    mma_gemm<3><<<dim3(12, 128, 1), blk, SHMB>>>(pH, pWqkvT, pQKV, nullptr, nullptr,
        C_, C_, C_, 3 * C_, 0, 0, 0, 0, 0, 0, 1, 1.0f);

    // v transpose per (b,h)
    transpose_v<<<dim3(T_ / 32, HS_ / 32, B_ * H_), dim3(32, 8)>>>(pQKV);

    // scores = scale * q k^T  (A=q cols [0,512), B=k cols [512,1024))
    mma_gemm<0><<<dim3(16, 16, B_ * H_), blk, SHMB>>>(pQKV, pQKV + C_, pAtt, nullptr, nullptr,
        HS_, 3 * C_, 3 * C_, T_,
        (long long)T_ * 3 * C_, HS_,
        (long long)T_ * 3 * C_, HS_,
        (long long)H_ * T_ * T_, (long long)T_ * T_,
        H_, 0.0625f);

    // masked softmax
    softmax_kernel<<<B_ * H_ * T_, 256>>>(smask);

    // o = att @ v  (B = vT [HS,T] per (b,h)), concat-head output into pH
    mma_gemm<3><<<dim3(2, 16, B_ * H_), blk, SHMB>>>(pAtt, pVT, pH, nullptr, nullptr,
        T_, T_, T_, C_,
        (long long)H_ * T_ * T_, (long long)T_ * T_,
        (long long)H_ * HS_ * T_, (long long)HS_ * T_,
        (long long)T_ * C_, HS_,
        H_, 1.0f);

    // x1 = x + o @ Wproj + bproj
    mma_gemm<1><<<dim3(4, 128, 1), blk, SHMB>>>(pH, pWprojT, pX1, bproj, x,
        C_, C_, C_, C_, 0, 0, 0, 0, 0, 0, 1, 1.0f);

    // LN2
    ln_kernel<<<BT_, 256>>>(pX1, g2, be2, pH);

    // f1 = relu(h2 @ W1 + b1)
    mma_gemm<2><<<dim3(16, 128, 1), blk, SHMB>>>(pH, pW1T, pF1, b1, nullptr,
        C_, C_, C_, 4 * C_, 0, 0, 0, 0, 0, 0, 1, 1.0f);

    // out = x1 + f1 @ W2 + b2
    mma_gemm<1><<<dim3(4, 128, 1), blk, SHMB>>>(pF1, pW2T, out, b2, pX1,
        4 * C_, 4 * C_, 4 * C_, C_, 0, 0, 0, 0, 0, 0, 1, 1.0f);
}

// round 4
// speedup vs baseline: 6.6799x; 1.7617x over previous
#include <cuda_runtime.h>
#include <cuda_fp16.h>
#include <cstdint>
#include <math.h>

#define B_  8
#define T_  2048
#define C_  512
#define H_  2
#define HS_ 256
#define BT_ (B_ * T_)
#define EPS_ 1e-5f

// ---------------- device scratch (static, allocation-free) ----------------
__device__ __align__(256) __half g_h[BT_ * C_];                       // LN out / attn-out
__device__ __align__(256) __half g_qkv[(size_t)BT_ * 3 * C_];         // [BT, 1536] q|k|v
__device__ __align__(256) __half g_vT[(size_t)B_ * H_ * HS_ * T_];    // v transposed per (b,h)
__device__ __align__(256) __half g_att[(size_t)B_ * H_ * T_ * T_];    // attention (fp16)
__device__ __align__(256) float  g_x1[BT_ * C_];                      // residual after attention
__device__ __align__(256) __half g_f1[(size_t)BT_ * 4 * C_];          // FFN intermediate
__device__ __align__(256) __half g_wqkvT[3 * C_ * C_];                // [1536, 512]
__device__ __align__(256) __half g_wprojT[C_ * C_];                   // [512, 512]
__device__ __align__(256) __half g_w1T[4 * C_ * C_];                  // [2048, 512]
__device__ __align__(256) __half g_w2T[4 * C_ * C_];                  // [512, 2048]

// ---------------- small PTX helpers ----------------
__device__ __forceinline__ uint32_t su32(const void* p) {
    uint32_t a;
    asm("{ .reg .u64 t; cvta.to.shared.u64 t, %1; cvt.u32.u64 %0, t; }" : "=r"(a) : "l"(p));
    return a;
}
__device__ __forceinline__ void cp16(uint32_t dst, const void* src) {
    asm volatile("cp.async.cg.shared.global [%0], [%1], 16;" :: "r"(dst), "l"(src));
}
__device__ __forceinline__ void ldsm4(uint32_t* r, uint32_t a) {
    asm volatile("ldmatrix.sync.aligned.m8n8.x4.shared.b16 {%0,%1,%2,%3}, [%4];"
                 : "=r"(r[0]), "=r"(r[1]), "=r"(r[2]), "=r"(r[3]) : "r"(a));
}
__device__ __forceinline__ void mma_f16(float* d, const uint32_t* a, uint32_t b0, uint32_t b1) {
    asm volatile(
        "mma.sync.aligned.m16n8k16.row.col.f32.f16.f16.f32 "
        "{%0,%1,%2,%3}, {%4,%5,%6,%7}, {%8,%9}, {%0,%1,%2,%3};"
        : "+f"(d[0]), "+f"(d[1]), "+f"(d[2]), "+f"(d[3])
        : "r"(a[0]), "r"(a[1]), "r"(a[2]), "r"(a[3]), "r"(b0), "r"(b1));
}

// ---------------- weight repacks (transpose + fp16 round) ----------------
__global__ void repack_qkvT(const float* __restrict__ Wq, const float* __restrict__ Wk,
                            const float* __restrict__ Wv) {
    int idx = blockIdx.x * blockDim.x + threadIdx.x;     // [0, 1536*512)
    if (idx >= 3 * C_ * C_) return;
    int n = idx / C_, k = idx % C_;
    int part = n / C_;
    int nn = n % C_;
    int h = nn / HS_, d = nn % HS_;
    const float* W = (part == 0) ? Wq : ((part == 1) ? Wk : Wv);
    g_wqkvT[idx] = __float2half_rn(W[(size_t)h * C_ * HS_ + (size_t)k * HS_ + d]);
}

// out[n*K+k] = fp16(in[k*N+n]), tiled
__global__ void transpose_w(const float* __restrict__ in, __half* __restrict__ out,
                            int K, int N) {
    __shared__ float t[32][33];
    int n0 = blockIdx.x * 32, k0 = blockIdx.y * 32;
    int tx = threadIdx.x, ty = threadIdx.y;  // 32x8
#pragma unroll
    for (int i = 0; i < 32; i += 8)
        t[ty + i][tx] = in[(size_t)(k0 + ty + i) * N + n0 + tx];
    __syncthreads();
#pragma unroll
    for (int i = 0; i < 32; i += 8)
        out[(size_t)(n0 + ty + i) * K + k0 + tx] = __float2half_rn(t[tx][ty + i]);
}

// vT[(b*H+h)*HS + d][s] = qkv[b*T+s][1024 + h*256 + d]
__global__ void transpose_v(const __half* __restrict__ qkv) {
    __shared__ __half t[32][34];
    int z = blockIdx.z;
    int b = z / H_, h = z % H_;
    int s0 = blockIdx.x * 32, d0 = blockIdx.y * 32;
    int tx = threadIdx.x, ty = threadIdx.y;
    const __half* in = qkv + (size_t)b * T_ * 1536 + 2 * C_ + h * HS_;
#pragma unroll
    for (int i = 0; i < 32; i += 8)
        t[ty + i][tx] = in[(size_t)(s0 + ty + i) * 1536 + d0 + tx];
    __syncthreads();
    __half* out = g_vT + ((size_t)z * HS_ + d0) * T_ + s0;
#pragma unroll
    for (int i = 0; i < 32; i += 8)
        out[(size_t)(ty + i) * T_ + tx] = t[tx][ty + i];
}

// ---------------- LayerNorm: one block per row of C=512 -> fp16 out ----------------
__global__ void ln_kernel(const float* __restrict__ x, const float* __restrict__ g,
                          const float* __restrict__ b, __half* __restrict__ out) {
    int row = blockIdx.x;
    int tid = threadIdx.x;  // 256 threads
    const float* xr = x + (size_t)row * C_;
    float v0 = xr[tid], v1 = xr[tid + 256];
    float s = v0 + v1, ss = v0 * v0 + v1 * v1;
#pragma unroll
    for (int o = 16; o; o >>= 1) {
        s  += __shfl_xor_sync(0xffffffffu, s, o);
        ss += __shfl_xor_sync(0xffffffffu, ss, o);
    }
    __shared__ float sh_s[8], sh_ss[8];
    if ((tid & 31) == 0) { sh_s[tid >> 5] = s; sh_ss[tid >> 5] = ss; }
    __syncthreads();
    s = 0.f; ss = 0.f;
#pragma unroll
    for (int i = 0; i < 8; i++) { s += sh_s[i]; ss += sh_ss[i]; }
    float mean = s * (1.0f / C_);
    float var  = ss * (1.0f / C_) - mean * mean;
    float inv  = rsqrtf(var + EPS_);
    __half* orow = out + (size_t)row * C_;
    orow[tid]       = __float2half_rn((v0 - mean) * inv * g[tid]       + b[tid]);
    orow[tid + 256] = __float2half_rn((v1 - mean) * inv * g[tid + 256] + b[tid + 256]);
}

// ---------------- masked softmax over att rows (T=2048), fp16 in/out --------------
__global__ void softmax_kernel(const int* __restrict__ mask) {
    int r = blockIdx.x;             // (b*H + h)*T + t
    int t = r % T_;
    int b = (r / T_) / H_;
    __half2* row2 = (__half2*)(g_att + (size_t)r * T_);
    const int2* mrow = (const int2*)(mask + (size_t)(b * T_ + t) * T_);
    int tid = threadIdx.x;          // 256 threads, 4 half2 each
    float v[8];
    float mx = -1e30f;
#pragma unroll
    for (int i = 0; i < 4; i++) {
        int s = tid + i * 256;
        float2 f = __half22float2(row2[s]);
        int2 mm = mrow[s];
        if (mm.x == 0) f.x = -1e30f;
        if (mm.y == 0) f.y = -1e30f;
        v[2 * i] = f.x; v[2 * i + 1] = f.y;
        mx = fmaxf(mx, fmaxf(f.x, f.y));
    }
#pragma unroll
    for (int o = 16; o; o >>= 1) mx = fmaxf(mx, __shfl_xor_sync(0xffffffffu, mx, o));
    __shared__ float shm[8];
    if ((tid & 31) == 0) shm[tid >> 5] = mx;
    __syncthreads();
    mx = shm[0];
#pragma unroll
    for (int i = 1; i < 8; i++) mx = fmaxf(mx, shm[i]);
    float sum = 0.f;
#pragma unroll
    for (int i = 0; i < 8; i++) { v[i] = __expf(v[i] - mx); sum += v[i]; }
#pragma unroll
    for (int o = 16; o; o >>= 1) sum += __shfl_xor_sync(0xffffffffu, sum, o);
    __shared__ float shs[8];
    if ((tid & 31) == 0) shs[tid >> 5] = sum;
    __syncthreads();
    sum = 0.f;
#pragma unroll
    for (int i = 0; i < 8; i++) sum += shs[i];
    float inv = 1.0f / sum;
#pragma unroll
    for (int i = 0; i < 4; i++)
        row2[tid + i * 256] = __floats2half2_rn(v[2 * i] * inv, v[2 * i + 1] * inv);
}

// ---------------- mma.sync fp16 NT GEMM: 128x128 block tile, K=32/stage -------------
// A [M,K] fp16 row-major (lda), B [N,K] fp16 row-major (ldb). 4 warps, warp tile
// 64x64 (m16n8k16), ldmatrix.x4 fragment loads, 2-stage cp.async, 2 CTAs/SM.
// Smem rows stride 80B (64B data + 16B pad) -> conflict-free ldmatrix phases.
// MODE 0: att = fp16(alpha*acc)          MODE 1: Cf32 = acc + bias + res
// MODE 2: f1 = fp16(relu(acc+bias))      MODE 3: C = fp16(acc)
#define SROWB  80
#define TILEB  (128 * SROWB)        // 10240 B
#define STAGEB (2 * TILEB)          // 20480 B
#define SHMB   (2 * STAGEB)         // 40960 B

template <int MODE>
__global__ void __launch_bounds__(128, 2)
mma_gemm(const __half* __restrict__ A, const __half* __restrict__ Bm, void* __restrict__ Cout,
         const float* __restrict__ bias, const float* __restrict__ res,
         int K, int lda, int ldb, int ldc,
         long long sA1, long long sA2, long long sB1, long long sB2,
         long long sC1, long long sC2, int bdiv, float alpha) {
    extern __shared__ char smraw[];
    const uint32_t sbase = su32(smraw);
    const int tid = threadIdx.x, lane = tid & 31, wid = tid >> 5;
    const int wm = wid >> 1, wn = wid & 1;

    const int z1 = blockIdx.z / bdiv, z2 = blockIdx.z % bdiv;
    A  += (size_t)z1 * sA1 + (size_t)z2 * sA2;
    Bm += (size_t)z1 * sB1 + (size_t)z2 * sB2;
    const size_t coff = (size_t)z1 * sC1 + (size_t)z2 * sC2;
    const int m0 = blockIdx.y * 128, n0 = blockIdx.x * 128;

    float acc[4][8][4];
#pragma unroll
    for (int i = 0; i < 4; i++)
#pragma unroll
        for (int j = 0; j < 8; j++)
#pragma unroll
            for (int c = 0; c < 4; c++) acc[i][j][c] = 0.f;

    // gmem->smem: thread owns chunk c (16B = 8 halves), rows r0+32i
    const int c = tid & 3, r0 = tid >> 2;
    const uint32_t dA0 = sbase + (uint32_t)(r0 * SROWB + c * 16);
    const uint32_t dB0 = dA0 + TILEB;
    const __half* gA0 = A  + (size_t)(m0 + r0) * lda + c * 8;
    const __half* gB0 = Bm + (size_t)(n0 + r0) * ldb + c * 8;
    const int nk = K >> 5;

    // fragment smem bases (ldmatrix lane addressing)
    const uint32_t aF0 = sbase + (uint32_t)((wm * 64 + (lane & 15)) * SROWB + (lane >> 4) * 16);
    const uint32_t bF0 = sbase + TILEB +
        (uint32_t)((wn * 64 + (lane & 7) + ((lane >> 4) & 1) * 8) * SROWB + ((lane >> 3) & 1) * 16);

    // prologue: stage 0
#pragma unroll
    for (int t = 0; t < 4; t++) {
        cp16(dA0 + (uint32_t)(32 * t * SROWB), gA0 + (size_t)(32 * t) * lda);
        cp16(dB0 + (uint32_t)(32 * t * SROWB), gB0 + (size_t)(32 * t) * ldb);
    }
    asm volatile("cp.async.commit_group;");

    for (int j = 0; j < nk; j++) {
        if (j + 1 < nk) {
            const uint32_t soff = (uint32_t)(((j + 1) & 1) * STAGEB);
            const __half* ga = gA0 + (j + 1) * 32;
            const __half* gb = gB0 + (j + 1) * 32;
#pragma unroll
            for (int t = 0; t < 4; t++) {
                cp16(dA0 + soff + (uint32_t)(32 * t * SROWB), ga + (size_t)(32 * t) * lda);
                cp16(dB0 + soff + (uint32_t)(32 * t * SROWB), gb + (size_t)(32 * t) * ldb);
            }
        }
        asm volatile("cp.async.commit_group;");
        asm volatile("cp.async.wait_group 1;");       // stage j landed
        __syncthreads();

        const uint32_t sa = aF0 + (uint32_t)((j & 1) * STAGEB);
        const uint32_t sb = bF0 + (uint32_t)((j & 1) * STAGEB);
#pragma unroll
        for (int ks = 0; ks < 2; ks++) {
            uint32_t aR[4][4], bR[4][4];
#pragma unroll
            for (int mt = 0; mt < 4; mt++)
                ldsm4(aR[mt], sa + (uint32_t)(mt * 16 * SROWB + ks * 32));
#pragma unroll
            for (int np = 0; np < 4; np++)
                ldsm4(bR[np], sb + (uint32_t)(np * 16 * SROWB + ks * 32));
#pragma unroll
            for (int mt = 0; mt < 4; mt++)
#pragma unroll
                for (int nt = 0; nt < 8; nt++)
                    mma_f16(acc[mt][nt], aR[mt],
                            bR[nt >> 1][(nt & 1) * 2], bR[nt >> 1][(nt & 1) * 2 + 1]);
        }
        __syncthreads();   // before next iter overwrites the other buffer
    }

    // epilogue
    const int r = lane >> 2, cq = 2 * (lane & 3);
#pragma unroll
    for (int mt = 0; mt < 4; mt++) {
        const int row0 = m0 + wm * 64 + mt * 16 + r;
#pragma unroll
        for (int nt = 0; nt < 8; nt++) {
            const int col = n0 + wn * 64 + nt * 8 + cq;
            float v0 = acc[mt][nt][0], v1 = acc[mt][nt][1];
            float v2 = acc[mt][nt][2], v3 = acc[mt][nt][3];
            if (MODE == 1) {
                float* Cm = (float*)Cout + coff;
                float b0 = bias[col], b1 = bias[col + 1];
                const float* r0p = res + (size_t)row0 * ldc + col;
                const float* r1p = res + (size_t)(row0 + 8) * ldc + col;
                float2 o0, o1;
                o0.x = v0 + b0 + r0p[0]; o0.y = v1 + b1 + r0p[1];
                o1.x = v2 + b0 + r1p[0]; o1.y = v3 + b1 + r1p[1];
                *(float2*)(Cm + (size_t)row0 * ldc + col) = o0;
                *(float2*)(Cm + (size_t)(row0 + 8) * ldc + col) = o1;
            } else {
                __half* Cm = (__half*)Cout + coff;
                __half2 h0, h1;
                if (MODE == 0) {
                    h0 = __floats2half2_rn(v0 * alpha, v1 * alpha);
                    h1 = __floats2half2_rn(v2 * alpha, v3 * alpha);
                } else if (MODE == 2) {
                    float b0 = bias[col], b1 = bias[col + 1];
                    h0 = __floats2half2_rn(fmaxf(v0 + b0, 0.f), fmaxf(v1 + b1, 0.f));
                    h1 = __floats2half2_rn(fmaxf(v2 + b0, 0.f), fmaxf(v3 + b1, 0.f));
                } else {
                    h0 = __floats2half2_rn(v0, v1);
                    h1 = __floats2half2_rn(v2, v3);
                }
                *(__half2*)(Cm + (size_t)row0 * ldc + col) = h0;
                *(__half2*)(Cm + (size_t)(row0 + 8) * ldc + col) = h1;
            }
        }
    }
}

// ---------------- host launcher ----------------
extern "C" void kernel_launch(void* const* d_in, const int* in_sizes, int n_in,
                              void* d_out, int out_size) {
    const float* x     = (const float*)d_in[0];
    const int*   smask = (const int*)d_in[1];
    const float* Wq    = (const float*)d_in[2];
    const float* Wk    = (const float*)d_in[3];
    const float* Wv    = (const float*)d_in[4];
    const float* Wproj = (const float*)d_in[5];
    const float* bproj = (const float*)d_in[6];
    const float* W1    = (const float*)d_in[7];
    const float* b1    = (const float*)d_in[8];
    const float* W2    = (const float*)d_in[9];
    const float* b2    = (const float*)d_in[10];
    const float* g1    = (const float*)d_in[11];
    const float* be1   = (const float*)d_in[12];
    const float* g2    = (const float*)d_in[13];
    const float* be2   = (const float*)d_in[14];
    float* out = (float*)d_out;

    __half *pH, *pQKV, *pVT, *pAtt, *pF1, *pWqkvT, *pWprojT, *pW1T, *pW2T;
    float* pX1;
    cudaGetSymbolAddress((void**)&pH,      g_h);
    cudaGetSymbolAddress((void**)&pQKV,    g_qkv);
    cudaGetSymbolAddress((void**)&pVT,     g_vT);
    cudaGetSymbolAddress((void**)&pAtt,    g_att);
    cudaGetSymbolAddress((void**)&pX1,     g_x1);
    cudaGetSymbolAddress((void**)&pF1,     g_f1);
    cudaGetSymbolAddress((void**)&pWqkvT,  g_wqkvT);
    cudaGetSymbolAddress((void**)&pWprojT, g_wprojT);
    cudaGetSymbolAddress((void**)&pW1T,    g_w1T);
    cudaGetSymbolAddress((void**)&pW2T,    g_w2T);

    cudaFuncSetAttribute(mma_gemm<0>, cudaFuncAttributeMaxDynamicSharedMemorySize, SHMB);
    cudaFuncSetAttribute(mma_gemm<1>, cudaFuncAttributeMaxDynamicSharedMemorySize, SHMB);
    cudaFuncSetAttribute(mma_gemm<2>, cudaFuncAttributeMaxDynamicSharedMemorySize, SHMB);
    cudaFuncSetAttribute(mma_gemm<3>, cudaFuncAttributeMaxDynamicSharedMemorySize, SHMB);
    dim3 blk(128);

    // weight repacks (rounded to fp16)
    repack_qkvT<<<(3 * C_ * C_ + 255) / 256, 256>>>(Wq, Wk, Wv);
    transpose_w<<<dim3(C_ / 32, C_ / 32), dim3(32, 8)>>>(Wproj, pWprojT, C_, C_);
    transpose_w<<<dim3(4 * C_ / 32, C_ / 32), dim3(32, 8)>>>(W1, pW1T, C_, 4 * C_);
    transpose_w<<<dim3(C_ / 32, 4 * C_ / 32), dim3(32, 8)>>>(W2, pW2T, 4 * C_, C_);

    // LN1
    ln_kernel<<<BT_, 256>>>(x, g1, be1, pH);

    // QKV fused: [BT,512] x [1536,512]^T -> [BT,1536]
    mma_gemm<3><<<dim3(12, 128, 1), blk, SHMB>>>(pH, pWqkvT, pQKV, nullptr, nullptr,
        C_, C_, C_, 3 * C_, 0, 0, 0, 0, 0, 0, 1, 1.0f);

    // v transpose per (b,h)
    transpose_v<<<dim3(T_ / 32, HS_ / 32, B_ * H_), dim3(32, 8)>>>(pQKV);

    // scores = scale * q k^T  (A=q cols [0,512), B=k cols [512,1024))
    mma_gemm<0><<<dim3(16, 16, B_ * H_), blk, SHMB>>>(pQKV, pQKV + C_, pAtt, nullptr, nullptr,
        HS_, 3 * C_, 3 * C_, T_,
        (long long)T_ * 3 * C_, HS_,
        (long long)T_ * 3 * C_, HS_,
        (long long)H_ * T_ * T_, (long long)T_ * T_,
        H_, 0.0625f);

    // masked softmax
    softmax_kernel<<<B_ * H_ * T_, 256>>>(smask);

    // o = att @ v  (B = vT [HS,T] per (b,h)), concat-head output into pH
    mma_gemm<3><<<dim3(2, 16, B_ * H_), blk, SHMB>>>(pAtt, pVT, pH, nullptr, nullptr,
        T_, T_, T_, C_,
        (long long)H_ * T_ * T_, (long long)T_ * T_,
        (long long)H_ * HS_ * T_, (long long)HS_ * T_,
        (long long)T_ * C_, HS_,
        H_, 1.0f);

    // x1 = x + o @ Wproj + bproj
    mma_gemm<1><<<dim3(4, 128, 1), blk, SHMB>>>(pH, pWprojT, pX1, bproj, x,
        C_, C_, C_, C_, 0, 0, 0, 0, 0, 0, 1, 1.0f);

    // LN2
    ln_kernel<<<BT_, 256>>>(pX1, g2, be2, pH);

    // f1 = relu(h2 @ W1 + b1)
    mma_gemm<2><<<dim3(16, 128, 1), blk, SHMB>>>(pH, pW1T, pF1, b1, nullptr,
        C_, C_, C_, 4 * C_, 0, 0, 0, 0, 0, 0, 1, 1.0f);

    // out = x1 + f1 @ W2 + b2
    mma_gemm<1><<<dim3(4, 128, 1), blk, SHMB>>>(pF1, pW2T, out, b2, pX1,
        4 * C_, 4 * C_, 4 * C_, C_, 0, 0, 0, 0, 0, 0, 1, 1.0f);
}

// round 5
// speedup vs baseline: 6.9087x; 1.0343x over previous
#include <cuda_runtime.h>
#include <cuda_fp16.h>
#include <cstdint>
#include <math.h>

#define B_  8
#define T_  2048
#define C_  512
#define H_  2
#define HS_ 256
#define BT_ (B_ * T_)
#define EPS_ 1e-5f

// ---------------- device scratch (static, allocation-free) ----------------
__device__ __align__(256) __half g_h[BT_ * C_];                       // LN out / attn-out
__device__ __align__(256) __half g_qkv[(size_t)BT_ * 3 * C_];         // [BT, 1536] q|k|v
__device__ __align__(256) float  g_x1[BT_ * C_];                      // residual after attention
__device__ __align__(256) __half g_f1[(size_t)BT_ * 4 * C_];          // FFN intermediate
__device__ __align__(256) __half g_wqkvT[3 * C_ * C_];                // [1536, 512] (Wq pre-scaled)
__device__ __align__(256) __half g_wprojT[C_ * C_];                   // [512, 512]
__device__ __align__(256) __half g_w1T[4 * C_ * C_];                  // [2048, 512]
__device__ __align__(256) __half g_w2T[4 * C_ * C_];                  // [512, 2048]

// ---------------- small PTX helpers ----------------
__device__ __forceinline__ uint32_t su32(const void* p) {
    uint32_t a;
    asm("{ .reg .u64 t; cvta.to.shared.u64 t, %1; cvt.u32.u64 %0, t; }" : "=r"(a) : "l"(p));
    return a;
}
__device__ __forceinline__ void cp16(uint32_t dst, const void* src) {
    asm volatile("cp.async.cg.shared.global [%0], [%1], 16;" :: "r"(dst), "l"(src));
}
__device__ __forceinline__ void ldsm4(uint32_t* r, uint32_t a) {
    asm volatile("ldmatrix.sync.aligned.m8n8.x4.shared.b16 {%0,%1,%2,%3}, [%4];"
                 : "=r"(r[0]), "=r"(r[1]), "=r"(r[2]), "=r"(r[3]) : "r"(a));
}
__device__ __forceinline__ void ldsm4t(uint32_t* r, uint32_t a) {
    asm volatile("ldmatrix.sync.aligned.m8n8.x4.trans.shared.b16 {%0,%1,%2,%3}, [%4];"
                 : "=r"(r[0]), "=r"(r[1]), "=r"(r[2]), "=r"(r[3]) : "r"(a));
}
__device__ __forceinline__ void mma_f16(float* d, const uint32_t* a, uint32_t b0, uint32_t b1) {
    asm volatile(
        "mma.sync.aligned.m16n8k16.row.col.f32.f16.f16.f32 "
        "{%0,%1,%2,%3}, {%4,%5,%6,%7}, {%8,%9}, {%0,%1,%2,%3};"
        : "+f"(d[0]), "+f"(d[1]), "+f"(d[2]), "+f"(d[3])
        : "r"(a[0]), "r"(a[1]), "r"(a[2]), "r"(a[3]), "r"(b0), "r"(b1));
}

// ---------------- weight repacks (transpose + fp16 round) ----------------
// Wq is pre-scaled by 1/sqrt(HS)=1/16 (exact power of 2) so flash needs no scale.
__global__ void repack_qkvT(const float* __restrict__ Wq, const float* __restrict__ Wk,
                            const float* __restrict__ Wv) {
    int idx = blockIdx.x * blockDim.x + threadIdx.x;     // [0, 1536*512)
    if (idx >= 3 * C_ * C_) return;
    int n = idx / C_, k = idx % C_;
    int part = n / C_;
    int nn = n % C_;
    int h = nn / HS_, d = nn % HS_;
    const float* W = (part == 0) ? Wq : ((part == 1) ? Wk : Wv);
    float scale = (part == 0) ? 0.0625f : 1.0f;
    g_wqkvT[idx] = __float2half_rn(W[(size_t)h * C_ * HS_ + (size_t)k * HS_ + d] * scale);
}

// out[n*K+k] = fp16(in[k*N+n]), tiled
__global__ void transpose_w(const float* __restrict__ in, __half* __restrict__ out,
                            int K, int N) {
    __shared__ float t[32][33];
    int n0 = blockIdx.x * 32, k0 = blockIdx.y * 32;
    int tx = threadIdx.x, ty = threadIdx.y;  // 32x8
#pragma unroll
    for (int i = 0; i < 32; i += 8)
        t[ty + i][tx] = in[(size_t)(k0 + ty + i) * N + n0 + tx];
    __syncthreads();
#pragma unroll
    for (int i = 0; i < 32; i += 8)
        out[(size_t)(n0 + ty + i) * K + k0 + tx] = __float2half_rn(t[tx][ty + i]);
}

// ---------------- LayerNorm: one block per row of C=512 -> fp16 out ----------------
__global__ void ln_kernel(const float* __restrict__ x, const float* __restrict__ g,
                          const float* __restrict__ b, __half* __restrict__ out) {
    int row = blockIdx.x;
    int tid = threadIdx.x;  // 256 threads
    const float* xr = x + (size_t)row * C_;
    float v0 = xr[tid], v1 = xr[tid + 256];
    float s = v0 + v1, ss = v0 * v0 + v1 * v1;
#pragma unroll
    for (int o = 16; o; o >>= 1) {
        s  += __shfl_xor_sync(0xffffffffu, s, o);
        ss += __shfl_xor_sync(0xffffffffu, ss, o);
    }
    __shared__ float sh_s[8], sh_ss[8];
    if ((tid & 31) == 0) { sh_s[tid >> 5] = s; sh_ss[tid >> 5] = ss; }
    __syncthreads();
    s = 0.f; ss = 0.f;
#pragma unroll
    for (int i = 0; i < 8; i++) { s += sh_s[i]; ss += sh_ss[i]; }
    float mean = s * (1.0f / C_);
    float var  = ss * (1.0f / C_) - mean * mean;
    float inv  = rsqrtf(var + EPS_);
    __half* orow = out + (size_t)row * C_;
    orow[tid]       = __float2half_rn((v0 - mean) * inv * g[tid]       + b[tid]);
    orow[tid + 256] = __float2half_rn((v1 - mean) * inv * g[tid + 256] + b[tid + 256]);
}

// ---------------- fused flash attention -------------------------------------------
// CTA: 128 q rows x one (b,h). 8 warps x 16 rows. kv tiles of 64, double-buffered
// cp.async. Q staged once in smem. S kept in mma accumulators; converted in-register
// to fp16 A-fragments for PV. V loaded with ldmatrix.trans (no transpose pass).
// Online softmax in fp32. Output written to g_h in concat-head [B,T,C] fp16 layout.
#define QT_  128
#define KT_  64
#define SRH  264                       // smem row stride in halves (256 + 8 pad)
#define FLASH_SHM ((QT_ + 4 * KT_) * SRH * 2)   // Q + 2 stages of (K+V) = 202752 B

__global__ void __launch_bounds__(256, 1)
flash_kernel(const __half* __restrict__ qkv, const int* __restrict__ mask,
             __half* __restrict__ outh) {
    extern __shared__ __half sh[];
    const uint32_t sb = su32(sh);
    const int tid = threadIdx.x, lane = tid & 31, wid = tid >> 5;
    const int bh = blockIdx.y, b = bh >> 1, h = bh & 1;
    const int q0 = blockIdx.x * QT_;

    const uint32_t suQ = sb;
    const uint32_t suK0 = sb + (uint32_t)(QT_ * SRH * 2);
    const uint32_t stageB = (uint32_t)(2 * KT_ * SRH * 2);

    // ---- stage Q tile (128 x 256 halves) ----
    const int cc16 = tid & 31, rw = tid >> 5;
    {
        const __half* gq = qkv + ((size_t)(b * T_ + q0) + rw) * 1536 + h * HS_ + cc16 * 8;
        uint32_t dq = suQ + (uint32_t)(rw * SRH + cc16 * 8) * 2;
#pragma unroll
        for (int i = 0; i < 16; i++)
            cp16(dq + (uint32_t)(8 * i * SRH) * 2, gq + (size_t)(8 * i) * 1536);
    }
    const __half* gk = qkv + ((size_t)b * T_) * 1536 + C_ + h * HS_ + cc16 * 8;
    const __half* gv = gk + C_;

    // ---- prologue: kv tile 0 ----
    {
        uint32_t dst = suK0 + (uint32_t)(rw * SRH + cc16 * 8) * 2;
#pragma unroll
        for (int i = 0; i < 8; i++) {
            cp16(dst + (uint32_t)(8 * i * SRH) * 2, gk + (size_t)(rw + 8 * i) * 1536);
            cp16(dst + (uint32_t)((KT_ + 8 * i) * SRH) * 2, gv + (size_t)(rw + 8 * i) * 1536);
        }
    }
    asm volatile("cp.async.commit_group;");

    // fragment base addresses
    const uint32_t aAddr = suQ +
        (uint32_t)(((wid * 16 + (lane & 15)) * SRH) * 2 + (lane >> 4) * 16);
    const uint32_t kBase = suK0 +
        (uint32_t)((((lane & 7) + ((lane >> 4) & 1) * 8) * SRH) * 2 + ((lane >> 3) & 1) * 16);
    const uint32_t vBase = suK0 + (uint32_t)(KT_ * SRH * 2) +
        (uint32_t)((((lane & 7) + ((lane >> 3) & 1) * 8) * SRH) * 2 + (lane >> 4) * 16);

    float o[32][4];
#pragma unroll
    for (int i = 0; i < 32; i++)
#pragma unroll
        for (int c = 0; c < 4; c++) o[i][c] = 0.f;
    float m0 = -1e30f, m1 = -1e30f, l0 = 0.f, l1 = 0.f;

    const int qr = q0 + wid * 16 + (lane >> 2);
    const int* mrow0 = mask + ((size_t)b * T_ + qr) * T_;
    const int* mrow1 = mrow0 + 8 * T_;
    const int cq = 2 * (lane & 3);

    const int NJ = T_ / KT_;   // 32
    for (int j = 0; j < NJ; j++) {
        if (j + 1 < NJ) {
            const int kv1 = (j + 1) * KT_;
            uint32_t dst = suK0 + (uint32_t)((j + 1) & 1) * stageB +
                           (uint32_t)(rw * SRH + cc16 * 8) * 2;
#pragma unroll
            for (int i = 0; i < 8; i++) {
                cp16(dst + (uint32_t)(8 * i * SRH) * 2, gk + (size_t)(kv1 + rw + 8 * i) * 1536);
                cp16(dst + (uint32_t)((KT_ + 8 * i) * SRH) * 2,
                     gv + (size_t)(kv1 + rw + 8 * i) * 1536);
            }
        }
        asm volatile("cp.async.commit_group;");
        asm volatile("cp.async.wait_group 1;");    // tile j (and Q) resident
        __syncthreads();
        const uint32_t soff = (uint32_t)(j & 1) * stageB;

        // ---- S = Q K^T  (16 x 64 per warp) ----
        float s[8][4];
#pragma unroll
        for (int nt = 0; nt < 8; nt++)
#pragma unroll
            for (int c = 0; c < 4; c++) s[nt][c] = 0.f;
#pragma unroll
        for (int ks = 0; ks < 16; ks++) {
            uint32_t aR[4];
            ldsm4(aR, aAddr + ks * 32);
#pragma unroll
            for (int ng = 0; ng < 4; ng++) {
                uint32_t bR[4];
                ldsm4(bR, kBase + soff + (uint32_t)(16 * ng * SRH) * 2 + ks * 32);
                mma_f16(s[2 * ng],     aR, bR[0], bR[1]);
                mma_f16(s[2 * ng + 1], aR, bR[2], bR[3]);
            }
        }

        // ---- mask + online softmax ----
        const int kv0 = j * KT_;
        float mx0 = -1e30f, mx1 = -1e30f;
#pragma unroll
        for (int nt = 0; nt < 8; nt++) {
            int col = kv0 + nt * 8 + cq;
            int2 ma = *(const int2*)(mrow0 + col);
            int2 mb = *(const int2*)(mrow1 + col);
            if (ma.x == 0) s[nt][0] = -1e30f;
            if (ma.y == 0) s[nt][1] = -1e30f;
            if (mb.x == 0) s[nt][2] = -1e30f;
            if (mb.y == 0) s[nt][3] = -1e30f;
            mx0 = fmaxf(mx0, fmaxf(s[nt][0], s[nt][1]));
            mx1 = fmaxf(mx1, fmaxf(s[nt][2], s[nt][3]));
        }
        mx0 = fmaxf(mx0, __shfl_xor_sync(0xffffffffu, mx0, 1));
        mx0 = fmaxf(mx0, __shfl_xor_sync(0xffffffffu, mx0, 2));
        mx1 = fmaxf(mx1, __shfl_xor_sync(0xffffffffu, mx1, 1));
        mx1 = fmaxf(mx1, __shfl_xor_sync(0xffffffffu, mx1, 2));
        float mn0 = fmaxf(m0, mx0), mn1 = fmaxf(m1, mx1);
        float al0 = __expf(m0 - mn0), al1 = __expf(m1 - mn1);
        m0 = mn0; m1 = mn1;

        float rs0 = 0.f, rs1 = 0.f;
        uint32_t pH[8][2];
#pragma unroll
        for (int nt = 0; nt < 8; nt++) {
            float p0 = __expf(s[nt][0] - mn0), p1 = __expf(s[nt][1] - mn0);
            float p2 = __expf(s[nt][2] - mn1), p3 = __expf(s[nt][3] - mn1);
            rs0 += p0 + p1; rs1 += p2 + p3;
            __half2 h0 = __floats2half2_rn(p0, p1);
            __half2 h1 = __floats2half2_rn(p2, p3);
            pH[nt][0] = *(uint32_t*)&h0;
            pH[nt][1] = *(uint32_t*)&h1;
        }
        rs0 += __shfl_xor_sync(0xffffffffu, rs0, 1);
        rs0 += __shfl_xor_sync(0xffffffffu, rs0, 2);
        rs1 += __shfl_xor_sync(0xffffffffu, rs1, 1);
        rs1 += __shfl_xor_sync(0xffffffffu, rs1, 2);
        l0 = l0 * al0 + rs0;
        l1 = l1 * al1 + rs1;
#pragma unroll
        for (int nt = 0; nt < 32; nt++) {
            o[nt][0] *= al0; o[nt][1] *= al0;
            o[nt][2] *= al1; o[nt][3] *= al1;
        }

        // ---- O += P V ----
#pragma unroll
        for (int ks = 0; ks < 4; ks++) {
            uint32_t aF[4] = { pH[2 * ks][0], pH[2 * ks][1],
                               pH[2 * ks + 1][0], pH[2 * ks + 1][1] };
#pragma unroll
            for (int ng = 0; ng < 16; ng++) {
                uint32_t vR[4];
                ldsm4t(vR, vBase + soff + (uint32_t)(16 * ks * SRH + 16 * ng) * 2);
                mma_f16(o[2 * ng],     aF, vR[0], vR[1]);
                mma_f16(o[2 * ng + 1], aF, vR[2], vR[3]);
            }
        }
        __syncthreads();   // all warps done with buffer before next-iter overwrite
    }

    // ---- finalize + store (concat-head layout) ----
    float i0 = 1.f / l0, i1 = 1.f / l1;
    __half* orow0 = outh + ((size_t)(b * T_) + qr) * C_ + h * HS_;
    __half* orow1 = orow0 + 8 * C_;
#pragma unroll
    for (int nt = 0; nt < 32; nt++) {
        int col = nt * 8 + cq;
        __half2 w0 = __floats2half2_rn(o[nt][0] * i0, o[nt][1] * i0);
        __half2 w1 = __floats2half2_rn(o[nt][2] * i1, o[nt][3] * i1);
        *(__half2*)(orow0 + col) = w0;
        *(__half2*)(orow1 + col) = w1;
    }
}

// ---------------- mma.sync fp16 NT GEMM: 128x128 block tile, K=32/stage -------------
#define SROWB  80
#define TILEB  (128 * SROWB)
#define STAGEB (2 * TILEB)
#define SHMB   (2 * STAGEB)

template <int MODE>
__global__ void __launch_bounds__(128, 2)
mma_gemm(const __half* __restrict__ A, const __half* __restrict__ Bm, void* __restrict__ Cout,
         const float* __restrict__ bias, const float* __restrict__ res,
         int K, int lda, int ldb, int ldc, float alpha) {
    extern __shared__ char smraw[];
    const uint32_t sbase = su32(smraw);
    const int tid = threadIdx.x, lane = tid & 31, wid = tid >> 5;
    const int wm = wid >> 1, wn = wid & 1;

    const int m0 = blockIdx.y * 128, n0 = blockIdx.x * 128;

    float acc[4][8][4];
#pragma unroll
    for (int i = 0; i < 4; i++)
#pragma unroll
        for (int j = 0; j < 8; j++)
#pragma unroll
            for (int c = 0; c < 4; c++) acc[i][j][c] = 0.f;

    const int c = tid & 3, r0 = tid >> 2;
    const uint32_t dA0 = sbase + (uint32_t)(r0 * SROWB + c * 16);
    const uint32_t dB0 = dA0 + TILEB;
    const __half* gA0 = A  + (size_t)(m0 + r0) * lda + c * 8;
    const __half* gB0 = Bm + (size_t)(n0 + r0) * ldb + c * 8;
    const int nk = K >> 5;

    const uint32_t aF0 = sbase + (uint32_t)((wm * 64 + (lane & 15)) * SROWB + (lane >> 4) * 16);
    const uint32_t bF0 = sbase + TILEB +
        (uint32_t)((wn * 64 + (lane & 7) + ((lane >> 4) & 1) * 8) * SROWB + ((lane >> 3) & 1) * 16);

#pragma unroll
    for (int t = 0; t < 4; t++) {
        cp16(dA0 + (uint32_t)(32 * t * SROWB), gA0 + (size_t)(32 * t) * lda);
        cp16(dB0 + (uint32_t)(32 * t * SROWB), gB0 + (size_t)(32 * t) * ldb);
    }
    asm volatile("cp.async.commit_group;");

    for (int j = 0; j < nk; j++) {
        if (j + 1 < nk) {
            const uint32_t soff = (uint32_t)(((j + 1) & 1) * STAGEB);
            const __half* ga = gA0 + (j + 1) * 32;
            const __half* gb = gB0 + (j + 1) * 32;
#pragma unroll
            for (int t = 0; t < 4; t++) {
                cp16(dA0 + soff + (uint32_t)(32 * t * SROWB), ga + (size_t)(32 * t) * lda);
                cp16(dB0 + soff + (uint32_t)(32 * t * SROWB), gb + (size_t)(32 * t) * ldb);
            }
        }
        asm volatile("cp.async.commit_group;");
        asm volatile("cp.async.wait_group 1;");
        __syncthreads();

        const uint32_t sa = aF0 + (uint32_t)((j & 1) * STAGEB);
        const uint32_t sb = bF0 + (uint32_t)((j & 1) * STAGEB);
#pragma unroll
        for (int ks = 0; ks < 2; ks++) {
            uint32_t aR[4][4], bR[4][4];
#pragma unroll
            for (int mt = 0; mt < 4; mt++)
                ldsm4(aR[mt], sa + (uint32_t)(mt * 16 * SROWB + ks * 32));
#pragma unroll
            for (int np = 0; np < 4; np++)
                ldsm4(bR[np], sb + (uint32_t)(np * 16 * SROWB + ks * 32));
#pragma unroll
            for (int mt = 0; mt < 4; mt++)
#pragma unroll
                for (int nt = 0; nt < 8; nt++)
                    mma_f16(acc[mt][nt], aR[mt],
                            bR[nt >> 1][(nt & 1) * 2], bR[nt >> 1][(nt & 1) * 2 + 1]);
        }
        __syncthreads();
    }

    const int r = lane >> 2, cq = 2 * (lane & 3);
#pragma unroll
    for (int mt = 0; mt < 4; mt++) {
        const int row0 = m0 + wm * 64 + mt * 16 + r;
#pragma unroll
        for (int nt = 0; nt < 8; nt++) {
            const int col = n0 + wn * 64 + nt * 8 + cq;
            float v0 = acc[mt][nt][0], v1 = acc[mt][nt][1];
            float v2 = acc[mt][nt][2], v3 = acc[mt][nt][3];
            if (MODE == 1) {
                float* Cm = (float*)Cout;
                float b0 = bias[col], b1 = bias[col + 1];
                const float* r0p = res + (size_t)row0 * ldc + col;
                const float* r1p = res + (size_t)(row0 + 8) * ldc + col;
                float2 o0, o1;
                o0.x = v0 + b0 + r0p[0]; o0.y = v1 + b1 + r0p[1];
                o1.x = v2 + b0 + r1p[0]; o1.y = v3 + b1 + r1p[1];
                *(float2*)(Cm + (size_t)row0 * ldc + col) = o0;
                *(float2*)(Cm + (size_t)(row0 + 8) * ldc + col) = o1;
            } else {
                __half* Cm = (__half*)Cout;
                __half2 h0, h1;
                if (MODE == 2) {
                    float b0 = bias[col], b1 = bias[col + 1];
                    h0 = __floats2half2_rn(fmaxf(v0 + b0, 0.f), fmaxf(v1 + b1, 0.f));
                    h1 = __floats2half2_rn(fmaxf(v2 + b0, 0.f), fmaxf(v3 + b1, 0.f));
                } else {
                    h0 = __floats2half2_rn(v0, v1);
                    h1 = __floats2half2_rn(v2, v3);
                }
                *(__half2*)(Cm + (size_t)row0 * ldc + col) = h0;
                *(__half2*)(Cm + (size_t)(row0 + 8) * ldc + col) = h1;
            }
        }
    }
}

// ---------------- host launcher ----------------
extern "C" void kernel_launch(void* const* d_in, const int* in_sizes, int n_in,
                              void* d_out, int out_size) {
    const float* x     = (const float*)d_in[0];
    const int*   smask = (const int*)d_in[1];
    const float* Wq    = (const float*)d_in[2];
    const float* Wk    = (const float*)d_in[3];
    const float* Wv    = (const float*)d_in[4];
    const float* Wproj = (const float*)d_in[5];
    const float* bproj = (const float*)d_in[6];
    const float* W1    = (const float*)d_in[7];
    const float* b1    = (const float*)d_in[8];
    const float* W2    = (const float*)d_in[9];
    const float* b2    = (const float*)d_in[10];
    const float* g1    = (const float*)d_in[11];
    const float* be1   = (const float*)d_in[12];
    const float* g2    = (const float*)d_in[13];
    const float* be2   = (const float*)d_in[14];
    float* out = (float*)d_out;

    __half *pH, *pQKV, *pF1, *pWqkvT, *pWprojT, *pW1T, *pW2T;
    float* pX1;
    cudaGetSymbolAddress((void**)&pH,      g_h);
    cudaGetSymbolAddress((void**)&pQKV,    g_qkv);
    cudaGetSymbolAddress((void**)&pX1,     g_x1);
    cudaGetSymbolAddress((void**)&pF1,     g_f1);
    cudaGetSymbolAddress((void**)&pWqkvT,  g_wqkvT);
    cudaGetSymbolAddress((void**)&pWprojT, g_wprojT);
    cudaGetSymbolAddress((void**)&pW1T,    g_w1T);
    cudaGetSymbolAddress((void**)&pW2T,    g_w2T);

    cudaFuncSetAttribute(mma_gemm<1>, cudaFuncAttributeMaxDynamicSharedMemorySize, SHMB);
    cudaFuncSetAttribute(mma_gemm<2>, cudaFuncAttributeMaxDynamicSharedMemorySize, SHMB);
    cudaFuncSetAttribute(mma_gemm<3>, cudaFuncAttributeMaxDynamicSharedMemorySize, SHMB);
    cudaFuncSetAttribute(flash_kernel, cudaFuncAttributeMaxDynamicSharedMemorySize, FLASH_SHM);
    dim3 blk(128);

    // weight repacks (rounded to fp16; Wq pre-scaled 1/16)
    repack_qkvT<<<(3 * C_ * C_ + 255) / 256, 256>>>(Wq, Wk, Wv);
    transpose_w<<<dim3(C_ / 32, C_ / 32), dim3(32, 8)>>>(Wproj, pWprojT, C_, C_);
    transpose_w<<<dim3(4 * C_ / 32, C_ / 32), dim3(32, 8)>>>(W1, pW1T, C_, 4 * C_);
    transpose_w<<<dim3(C_ / 32, 4 * C_ / 32), dim3(32, 8)>>>(W2, pW2T, 4 * C_, C_);

    // LN1
    ln_kernel<<<BT_, 256>>>(x, g1, be1, pH);

    // QKV fused: [BT,512] x [1536,512]^T -> [BT,1536]
    mma_gemm<3><<<dim3(12, 128, 1), blk, SHMB>>>(pH, pWqkvT, pQKV, nullptr, nullptr,
        C_, C_, C_, 3 * C_, 1.0f);

    // fused flash attention -> pH (concat-head fp16)
    flash_kernel<<<dim3(T_ / QT_, B_ * H_), 256, FLASH_SHM>>>(pQKV, smask, pH);

    // x1 = x + o @ Wproj + bproj
    mma_gemm<1><<<dim3(4, 128, 1), blk, SHMB>>>(pH, pWprojT, pX1, bproj, x,
        C_, C_, C_, C_, 1.0f);

    // LN2
    ln_kernel<<<BT_, 256>>>(pX1, g2, be2, pH);

    // f1 = relu(h2 @ W1 + b1)
    mma_gemm<2><<<dim3(16, 128, 1), blk, SHMB>>>(pH, pW1T, pF1, b1, nullptr,
        C_, C_, C_, 4 * C_, 1.0f);

    // out = x1 + f1 @ W2 + b2
    mma_gemm<1><<<dim3(4, 128, 1), blk, SHMB>>>(pF1, pW2T, out, b2, pX1,
        4 * C_, 4 * C_, 4 * C_, C_, 1.0f);
}

// round 6
// speedup vs baseline: 6.9696x; 1.0088x over previous
#include <cuda_runtime.h>
#include <cuda_fp16.h>
#include <cstdint>
#include <math.h>

#define B_  8
#define T_  2048
#define C_  512
#define H_  2
#define HS_ 256
#define BT_ (B_ * T_)
#define EPS_ 1e-5f

// ---------------- device scratch (static, allocation-free) ----------------
__device__ __align__(256) __half g_h[BT_ * C_];                       // LN out / attn-out
__device__ __align__(256) __half g_qkv[(size_t)BT_ * 3 * C_];         // [BT, 1536] q|k|v
__device__ __align__(256) float  g_x1[BT_ * C_];                      // residual after attention
__device__ __align__(256) __half g_f1[(size_t)BT_ * 4 * C_];          // FFN intermediate
__device__ __align__(256) __half g_wqkvT[3 * C_ * C_];                // [1536, 512] (Wq pre-scaled)
__device__ __align__(256) __half g_wprojT[C_ * C_];                   // [512, 512]
__device__ __align__(256) __half g_w1T[4 * C_ * C_];                  // [2048, 512]
__device__ __align__(256) __half g_w2T[4 * C_ * C_];                  // [512, 2048]

// ---------------- small PTX helpers ----------------
__device__ __forceinline__ uint32_t su32(const void* p) {
    uint32_t a;
    asm("{ .reg .u64 t; cvta.to.shared.u64 t, %1; cvt.u32.u64 %0, t; }" : "=r"(a) : "l"(p));
    return a;
}
__device__ __forceinline__ void cp16(uint32_t dst, const void* src) {
    asm volatile("cp.async.cg.shared.global [%0], [%1], 16;" :: "r"(dst), "l"(src));
}
__device__ __forceinline__ void ldsm4(uint32_t* r, uint32_t a) {
    asm volatile("ldmatrix.sync.aligned.m8n8.x4.shared.b16 {%0,%1,%2,%3}, [%4];"
                 : "=r"(r[0]), "=r"(r[1]), "=r"(r[2]), "=r"(r[3]) : "r"(a));
}
__device__ __forceinline__ void ldsm4t(uint32_t* r, uint32_t a) {
    asm volatile("ldmatrix.sync.aligned.m8n8.x4.trans.shared.b16 {%0,%1,%2,%3}, [%4];"
                 : "=r"(r[0]), "=r"(r[1]), "=r"(r[2]), "=r"(r[3]) : "r"(a));
}
__device__ __forceinline__ void mma_f16(float* d, const uint32_t* a, uint32_t b0, uint32_t b1) {
    asm volatile(
        "mma.sync.aligned.m16n8k16.row.col.f32.f16.f16.f32 "
        "{%0,%1,%2,%3}, {%4,%5,%6,%7}, {%8,%9}, {%0,%1,%2,%3};"
        : "+f"(d[0]), "+f"(d[1]), "+f"(d[2]), "+f"(d[3])
        : "r"(a[0]), "r"(a[1]), "r"(a[2]), "r"(a[3]), "r"(b0), "r"(b1));
}

// ---------------- weight repacks (transpose + fp16 round) ----------------
// Wq pre-scaled by log2(e)/sqrt(HS) so flash works in base-2 (exp -> exp2).
#define QSCALE_ (0.0625f * 1.4426950408889634f)
__global__ void repack_qkvT(const float* __restrict__ Wq, const float* __restrict__ Wk,
                            const float* __restrict__ Wv) {
    int idx = blockIdx.x * blockDim.x + threadIdx.x;     // [0, 1536*512)
    if (idx >= 3 * C_ * C_) return;
    int n = idx / C_, k = idx % C_;
    int part = n / C_;
    int nn = n % C_;
    int h = nn / HS_, d = nn % HS_;
    const float* W = (part == 0) ? Wq : ((part == 1) ? Wk : Wv);
    float scale = (part == 0) ? QSCALE_ : 1.0f;
    g_wqkvT[idx] = __float2half_rn(W[(size_t)h * C_ * HS_ + (size_t)k * HS_ + d] * scale);
}

// out[n*K+k] = fp16(in[k*N+n]), tiled
__global__ void transpose_w(const float* __restrict__ in, __half* __restrict__ out,
                            int K, int N) {
    __shared__ float t[32][33];
    int n0 = blockIdx.x * 32, k0 = blockIdx.y * 32;
    int tx = threadIdx.x, ty = threadIdx.y;  // 32x8
#pragma unroll
    for (int i = 0; i < 32; i += 8)
        t[ty + i][tx] = in[(size_t)(k0 + ty + i) * N + n0 + tx];
    __syncthreads();
#pragma unroll
    for (int i = 0; i < 32; i += 8)
        out[(size_t)(n0 + ty + i) * K + k0 + tx] = __float2half_rn(t[tx][ty + i]);
}

// ---------------- LayerNorm: one block per row of C=512 -> fp16 out ----------------
__global__ void ln_kernel(const float* __restrict__ x, const float* __restrict__ g,
                          const float* __restrict__ b, __half* __restrict__ out) {
    int row = blockIdx.x;
    int tid = threadIdx.x;  // 256 threads
    const float* xr = x + (size_t)row * C_;
    float v0 = xr[tid], v1 = xr[tid + 256];
    float s = v0 + v1, ss = v0 * v0 + v1 * v1;
#pragma unroll
    for (int o = 16; o; o >>= 1) {
        s  += __shfl_xor_sync(0xffffffffu, s, o);
        ss += __shfl_xor_sync(0xffffffffu, ss, o);
    }
    __shared__ float sh_s[8], sh_ss[8];
    if ((tid & 31) == 0) { sh_s[tid >> 5] = s; sh_ss[tid >> 5] = ss; }
    __syncthreads();
    s = 0.f; ss = 0.f;
#pragma unroll
    for (int i = 0; i < 8; i++) { s += sh_s[i]; ss += sh_ss[i]; }
    float mean = s * (1.0f / C_);
    float var  = ss * (1.0f / C_) - mean * mean;
    float inv  = rsqrtf(var + EPS_);
    __half* orow = out + (size_t)row * C_;
    orow[tid]       = __float2half_rn((v0 - mean) * inv * g[tid]       + b[tid]);
    orow[tid + 256] = __float2half_rn((v1 - mean) * inv * g[tid + 256] + b[tid + 256]);
}

// ---------------- fused flash attention (base-2 online softmax) ---------------------
// CTA: 128 q rows x one (b,h). 8 warps x 16 rows. kv tiles of 64, double-buffered
// cp.async. Q staged once in smem. S in mma accumulators; p = h2exp2(s - m) packed
// fp16 directly as PV A-fragments. O-rescale deferred (skipped when no new max).
#define QT_  128
#define KT_  64
#define SRH  264                       // smem row stride in halves (256 + 8 pad)
#define FLASH_SHM ((QT_ + 4 * KT_) * SRH * 2)   // Q + 2 stages of (K+V) = 202752 B

__global__ void __launch_bounds__(256, 1)
flash_kernel(const __half* __restrict__ qkv, const int* __restrict__ mask,
             __half* __restrict__ outh) {
    extern __shared__ __half sh[];
    const uint32_t sb = su32(sh);
    const int tid = threadIdx.x, lane = tid & 31, wid = tid >> 5;
    const int bh = blockIdx.y, b = bh >> 1, h = bh & 1;
    const int q0 = blockIdx.x * QT_;

    const uint32_t suQ = sb;
    const uint32_t suK0 = sb + (uint32_t)(QT_ * SRH * 2);
    const uint32_t stageB = (uint32_t)(2 * KT_ * SRH * 2);

    // ---- stage Q tile (128 x 256 halves) ----
    const int cc16 = tid & 31, rw = tid >> 5;
    {
        const __half* gq = qkv + ((size_t)(b * T_ + q0) + rw) * 1536 + h * HS_ + cc16 * 8;
        uint32_t dq = suQ + (uint32_t)(rw * SRH + cc16 * 8) * 2;
#pragma unroll
        for (int i = 0; i < 16; i++)
            cp16(dq + (uint32_t)(8 * i * SRH) * 2, gq + (size_t)(8 * i) * 1536);
    }
    const __half* gk = qkv + ((size_t)b * T_) * 1536 + C_ + h * HS_ + cc16 * 8;
    const __half* gv = gk + C_;

    // ---- prologue: kv tile 0 ----
    {
        uint32_t dst = suK0 + (uint32_t)(rw * SRH + cc16 * 8) * 2;
#pragma unroll
        for (int i = 0; i < 8; i++) {
            cp16(dst + (uint32_t)(8 * i * SRH) * 2, gk + (size_t)(rw + 8 * i) * 1536);
            cp16(dst + (uint32_t)((KT_ + 8 * i) * SRH) * 2, gv + (size_t)(rw + 8 * i) * 1536);
        }
    }
    asm volatile("cp.async.commit_group;");

    // fragment base addresses
    const uint32_t aAddr = suQ +
        (uint32_t)(((wid * 16 + (lane & 15)) * SRH) * 2 + (lane >> 4) * 16);
    const uint32_t kBase = suK0 +
        (uint32_t)((((lane & 7) + ((lane >> 4) & 1) * 8) * SRH) * 2 + ((lane >> 3) & 1) * 16);
    const uint32_t vBase = suK0 + (uint32_t)(KT_ * SRH * 2) +
        (uint32_t)((((lane & 7) + ((lane >> 3) & 1) * 8) * SRH) * 2 + (lane >> 4) * 16);

    float o[32][4];
#pragma unroll
    for (int i = 0; i < 32; i++)
#pragma unroll
        for (int c = 0; c < 4; c++) o[i][c] = 0.f;
    float m0 = -1e30f, m1 = -1e30f, l0 = 0.f, l1 = 0.f;

    const int qr = q0 + wid * 16 + (lane >> 2);
    const int* mrow0 = mask + ((size_t)b * T_ + qr) * T_;
    const int* mrow1 = mrow0 + 8 * T_;
    const int cq = 2 * (lane & 3);

    const int NJ = T_ / KT_;   // 32
    for (int j = 0; j < NJ; j++) {
        if (j + 1 < NJ) {
            const int kv1 = (j + 1) * KT_;
            uint32_t dst = suK0 + (uint32_t)((j + 1) & 1) * stageB +
                           (uint32_t)(rw * SRH + cc16 * 8) * 2;
#pragma unroll
            for (int i = 0; i < 8; i++) {
                cp16(dst + (uint32_t)(8 * i * SRH) * 2, gk + (size_t)(kv1 + rw + 8 * i) * 1536);
                cp16(dst + (uint32_t)((KT_ + 8 * i) * SRH) * 2,
                     gv + (size_t)(kv1 + rw + 8 * i) * 1536);
            }
        }
        asm volatile("cp.async.commit_group;");
        asm volatile("cp.async.wait_group 1;");    // tile j (and Q) resident
        __syncthreads();
        const uint32_t soff = (uint32_t)(j & 1) * stageB;

        // ---- S = Q K^T  (16 x 64 per warp) ----
        float s[8][4];
#pragma unroll
        for (int nt = 0; nt < 8; nt++)
#pragma unroll
            for (int c = 0; c < 4; c++) s[nt][c] = 0.f;
#pragma unroll
        for (int ks = 0; ks < 16; ks++) {
            uint32_t aR[4];
            ldsm4(aR, aAddr + ks * 32);
#pragma unroll
            for (int ng = 0; ng < 4; ng++) {
                uint32_t bR[4];
                ldsm4(bR, kBase + soff + (uint32_t)(16 * ng * SRH) * 2 + ks * 32);
                mma_f16(s[2 * ng],     aR, bR[0], bR[1]);
                mma_f16(s[2 * ng + 1], aR, bR[2], bR[3]);
            }
        }

        // ---- mask + online softmax (base-2) ----
        const int kv0 = j * KT_;
        float mx0 = -1e30f, mx1 = -1e30f;
#pragma unroll
        for (int nt = 0; nt < 8; nt++) {
            int col = kv0 + nt * 8 + cq;
            int2 ma = *(const int2*)(mrow0 + col);
            int2 mb = *(const int2*)(mrow1 + col);
            if (ma.x == 0) s[nt][0] = -1e30f;
            if (ma.y == 0) s[nt][1] = -1e30f;
            if (mb.x == 0) s[nt][2] = -1e30f;
            if (mb.y == 0) s[nt][3] = -1e30f;
            mx0 = fmaxf(mx0, fmaxf(s[nt][0], s[nt][1]));
            mx1 = fmaxf(mx1, fmaxf(s[nt][2], s[nt][3]));
        }
        mx0 = fmaxf(mx0, __shfl_xor_sync(0xffffffffu, mx0, 1));
        mx0 = fmaxf(mx0, __shfl_xor_sync(0xffffffffu, mx0, 2));
        mx1 = fmaxf(mx1, __shfl_xor_sync(0xffffffffu, mx1, 1));
        mx1 = fmaxf(mx1, __shfl_xor_sync(0xffffffffu, mx1, 2));
        float mn0 = fmaxf(m0, mx0), mn1 = fmaxf(m1, mx1);
        float al0 = exp2f(m0 - mn0), al1 = exp2f(m1 - mn1);   // ==1.0f when no new max
        m0 = mn0; m1 = mn1;

        float rs0 = 0.f, rs1 = 0.f;
        uint32_t pH[8][2];
#pragma unroll
        for (int nt = 0; nt < 8; nt++) {
            __half2 e01 = h2exp2(__floats2half2_rn(s[nt][0] - mn0, s[nt][1] - mn0));
            __half2 e23 = h2exp2(__floats2half2_rn(s[nt][2] - mn1, s[nt][3] - mn1));
            pH[nt][0] = *(uint32_t*)&e01;
            pH[nt][1] = *(uint32_t*)&e23;
            float2 f01 = __half22float2(e01), f23 = __half22float2(e23);
            rs0 += f01.x + f01.y;
            rs1 += f23.x + f23.y;
        }
        rs0 += __shfl_xor_sync(0xffffffffu, rs0, 1);
        rs0 += __shfl_xor_sync(0xffffffffu, rs0, 2);
        rs1 += __shfl_xor_sync(0xffffffffu, rs1, 1);
        rs1 += __shfl_xor_sync(0xffffffffu, rs1, 2);
        l0 = l0 * al0 + rs0;
        l1 = l1 * al1 + rs1;
        if (__any_sync(0xffffffffu, (al0 != 1.f) | (al1 != 1.f))) {
#pragma unroll
            for (int nt = 0; nt < 32; nt++) {
                o[nt][0] *= al0; o[nt][1] *= al0;
                o[nt][2] *= al1; o[nt][3] *= al1;
            }
        }

        // ---- O += P V ----
#pragma unroll
        for (int ks = 0; ks < 4; ks++) {
            uint32_t aF[4] = { pH[2 * ks][0], pH[2 * ks][1],
                               pH[2 * ks + 1][0], pH[2 * ks + 1][1] };
#pragma unroll
            for (int ng = 0; ng < 16; ng++) {
                uint32_t vR[4];
                ldsm4t(vR, vBase + soff + (uint32_t)(16 * ks * SRH + 16 * ng) * 2);
                mma_f16(o[2 * ng],     aF, vR[0], vR[1]);
                mma_f16(o[2 * ng + 1], aF, vR[2], vR[3]);
            }
        }
        __syncthreads();   // all warps done with buffer before next-iter overwrite
    }

    // ---- finalize + store (concat-head layout) ----
    float i0 = 1.f / l0, i1 = 1.f / l1;
    __half* orow0 = outh + ((size_t)(b * T_) + qr) * C_ + h * HS_;
    __half* orow1 = orow0 + 8 * C_;
#pragma unroll
    for (int nt = 0; nt < 32; nt++) {
        int col = nt * 8 + cq;
        __half2 w0 = __floats2half2_rn(o[nt][0] * i0, o[nt][1] * i0);
        __half2 w1 = __floats2half2_rn(o[nt][2] * i1, o[nt][3] * i1);
        *(__half2*)(orow0 + col) = w0;
        *(__half2*)(orow1 + col) = w1;
    }
}

// ---------------- mma.sync fp16 NT GEMM: 128x128 block tile, K=32/stage -------------
#define SROWB  80
#define TILEB  (128 * SROWB)
#define STAGEB (2 * TILEB)
#define SHMB   (2 * STAGEB)

template <int MODE>
__global__ void __launch_bounds__(128, 2)
mma_gemm(const __half* __restrict__ A, const __half* __restrict__ Bm, void* __restrict__ Cout,
         const float* __restrict__ bias, const float* __restrict__ res,
         int K, int lda, int ldb, int ldc, float alpha) {
    extern __shared__ char smraw[];
    const uint32_t sbase = su32(smraw);
    const int tid = threadIdx.x, lane = tid & 31, wid = tid >> 5;
    const int wm = wid >> 1, wn = wid & 1;

    const int m0 = blockIdx.y * 128, n0 = blockIdx.x * 128;

    float acc[4][8][4];
#pragma unroll
    for (int i = 0; i < 4; i++)
#pragma unroll
        for (int j = 0; j < 8; j++)
#pragma unroll
            for (int c = 0; c < 4; c++) acc[i][j][c] = 0.f;

    const int c = tid & 3, r0 = tid >> 2;
    const uint32_t dA0 = sbase + (uint32_t)(r0 * SROWB + c * 16);
    const uint32_t dB0 = dA0 + TILEB;
    const __half* gA0 = A  + (size_t)(m0 + r0) * lda + c * 8;
    const __half* gB0 = Bm + (size_t)(n0 + r0) * ldb + c * 8;
    const int nk = K >> 5;

    const uint32_t aF0 = sbase + (uint32_t)((wm * 64 + (lane & 15)) * SROWB + (lane >> 4) * 16);
    const uint32_t bF0 = sbase + TILEB +
        (uint32_t)((wn * 64 + (lane & 7) + ((lane >> 4) & 1) * 8) * SROWB + ((lane >> 3) & 1) * 16);

#pragma unroll
    for (int t = 0; t < 4; t++) {
        cp16(dA0 + (uint32_t)(32 * t * SROWB), gA0 + (size_t)(32 * t) * lda);
        cp16(dB0 + (uint32_t)(32 * t * SROWB), gB0 + (size_t)(32 * t) * ldb);
    }
    asm volatile("cp.async.commit_group;");

    for (int j = 0; j < nk; j++) {
        if (j + 1 < nk) {
            const uint32_t soff = (uint32_t)(((j + 1) & 1) * STAGEB);
            const __half* ga = gA0 + (j + 1) * 32;
            const __half* gb = gB0 + (j + 1) * 32;
#pragma unroll
            for (int t = 0; t < 4; t++) {
                cp16(dA0 + soff + (uint32_t)(32 * t * SROWB), ga + (size_t)(32 * t) * lda);
                cp16(dB0 + soff + (uint32_t)(32 * t * SROWB), gb + (size_t)(32 * t) * ldb);
            }
        }
        asm volatile("cp.async.commit_group;");
        asm volatile("cp.async.wait_group 1;");
        __syncthreads();

        const uint32_t sa = aF0 + (uint32_t)((j & 1) * STAGEB);
        const uint32_t sb = bF0 + (uint32_t)((j & 1) * STAGEB);
#pragma unroll
        for (int ks = 0; ks < 2; ks++) {
            uint32_t aR[4][4], bR[4][4];
#pragma unroll
            for (int mt = 0; mt < 4; mt++)
                ldsm4(aR[mt], sa + (uint32_t)(mt * 16 * SROWB + ks * 32));
#pragma unroll
            for (int np = 0; np < 4; np++)
                ldsm4(bR[np], sb + (uint32_t)(np * 16 * SROWB + ks * 32));
#pragma unroll
            for (int mt = 0; mt < 4; mt++)
#pragma unroll
                for (int nt = 0; nt < 8; nt++)
                    mma_f16(acc[mt][nt], aR[mt],
                            bR[nt >> 1][(nt & 1) * 2], bR[nt >> 1][(nt & 1) * 2 + 1]);
        }
        __syncthreads();
    }

    const int r = lane >> 2, cq = 2 * (lane & 3);
#pragma unroll
    for (int mt = 0; mt < 4; mt++) {
        const int row0 = m0 + wm * 64 + mt * 16 + r;
#pragma unroll
        for (int nt = 0; nt < 8; nt++) {
            const int col = n0 + wn * 64 + nt * 8 + cq;
            float v0 = acc[mt][nt][0], v1 = acc[mt][nt][1];
            float v2 = acc[mt][nt][2], v3 = acc[mt][nt][3];
            if (MODE == 1) {
                float* Cm = (float*)Cout;
                float b0 = bias[col], b1 = bias[col + 1];
                const float* r0p = res + (size_t)row0 * ldc + col;
                const float* r1p = res + (size_t)(row0 + 8) * ldc + col;
                float2 o0, o1;
                o0.x = v0 + b0 + r0p[0]; o0.y = v1 + b1 + r0p[1];
                o1.x = v2 + b0 + r1p[0]; o1.y = v3 + b1 + r1p[1];
                *(float2*)(Cm + (size_t)row0 * ldc + col) = o0;
                *(float2*)(Cm + (size_t)(row0 + 8) * ldc + col) = o1;
            } else {
                __half* Cm = (__half*)Cout;
                __half2 h0, h1;
                if (MODE == 2) {
                    float b0 = bias[col], b1 = bias[col + 1];
                    h0 = __floats2half2_rn(fmaxf(v0 + b0, 0.f), fmaxf(v1 + b1, 0.f));
                    h1 = __floats2half2_rn(fmaxf(v2 + b0, 0.f), fmaxf(v3 + b1, 0.f));
                } else {
                    h0 = __floats2half2_rn(v0, v1);
                    h1 = __floats2half2_rn(v2, v3);
                }
                *(__half2*)(Cm + (size_t)row0 * ldc + col) = h0;
                *(__half2*)(Cm + (size_t)(row0 + 8) * ldc + col) = h1;
            }
        }
    }
}

// ---------------- host launcher ----------------
extern "C" void kernel_launch(void* const* d_in, const int* in_sizes, int n_in,
                              void* d_out, int out_size) {
    const float* x     = (const float*)d_in[0];
    const int*   smask = (const int*)d_in[1];
    const float* Wq    = (const float*)d_in[2];
    const float* Wk    = (const float*)d_in[3];
    const float* Wv    = (const float*)d_in[4];
    const float* Wproj = (const float*)d_in[5];
    const float* bproj = (const float*)d_in[6];
    const float* W1    = (const float*)d_in[7];
    const float* b1    = (const float*)d_in[8];
    const float* W2    = (const float*)d_in[9];
    const float* b2    = (const float*)d_in[10];
    const float* g1    = (const float*)d_in[11];
    const float* be1   = (const float*)d_in[12];
    const float* g2    = (const float*)d_in[13];
    const float* be2   = (const float*)d_in[14];
    float* out = (float*)d_out;

    __half *pH, *pQKV, *pF1, *pWqkvT, *pWprojT, *pW1T, *pW2T;
    float* pX1;
    cudaGetSymbolAddress((void**)&pH,      g_h);
    cudaGetSymbolAddress((void**)&pQKV,    g_qkv);
    cudaGetSymbolAddress((void**)&pX1,     g_x1);
    cudaGetSymbolAddress((void**)&pF1,     g_f1);
    cudaGetSymbolAddress((void**)&pWqkvT,  g_wqkvT);
    cudaGetSymbolAddress((void**)&pWprojT, g_wprojT);
    cudaGetSymbolAddress((void**)&pW1T,    g_w1T);
    cudaGetSymbolAddress((void**)&pW2T,    g_w2T);

    cudaFuncSetAttribute(mma_gemm<1>, cudaFuncAttributeMaxDynamicSharedMemorySize, SHMB);
    cudaFuncSetAttribute(mma_gemm<2>, cudaFuncAttributeMaxDynamicSharedMemorySize, SHMB);
    cudaFuncSetAttribute(mma_gemm<3>, cudaFuncAttributeMaxDynamicSharedMemorySize, SHMB);
    cudaFuncSetAttribute(flash_kernel, cudaFuncAttributeMaxDynamicSharedMemorySize, FLASH_SHM);
    dim3 blk(128);

    // weight repacks (rounded to fp16; Wq pre-scaled log2e/16)
    repack_qkvT<<<(3 * C_ * C_ + 255) / 256, 256>>>(Wq, Wk, Wv);
    transpose_w<<<dim3(C_ / 32, C_ / 32), dim3(32, 8)>>>(Wproj, pWprojT, C_, C_);
    transpose_w<<<dim3(4 * C_ / 32, C_ / 32), dim3(32, 8)>>>(W1, pW1T, C_, 4 * C_);
    transpose_w<<<dim3(C_ / 32, 4 * C_ / 32), dim3(32, 8)>>>(W2, pW2T, 4 * C_, C_);

    // LN1
    ln_kernel<<<BT_, 256>>>(x, g1, be1, pH);

    // QKV fused: [BT,512] x [1536,512]^T -> [BT,1536]
    mma_gemm<3><<<dim3(12, 128, 1), blk, SHMB>>>(pH, pWqkvT, pQKV, nullptr, nullptr,
        C_, C_, C_, 3 * C_, 1.0f);

    // fused flash attention -> pH (concat-head fp16)
    flash_kernel<<<dim3(T_ / QT_, B_ * H_), 256, FLASH_SHM>>>(pQKV, smask, pH);

    // x1 = x + o @ Wproj + bproj
    mma_gemm<1><<<dim3(4, 128, 1), blk, SHMB>>>(pH, pWprojT, pX1, bproj, x,
        C_, C_, C_, C_, 1.0f);

    // LN2
    ln_kernel<<<BT_, 256>>>(pX1, g2, be2, pH);

    // f1 = relu(h2 @ W1 + b1)
    mma_gemm<2><<<dim3(16, 128, 1), blk, SHMB>>>(pH, pW1T, pF1, b1, nullptr,
        C_, C_, C_, 4 * C_, 1.0f);

    // out = x1 + f1 @ W2 + b2
    mma_gemm<1><<<dim3(4, 128, 1), blk, SHMB>>>(pF1, pW2T, out, b2, pX1,
        4 * C_, 4 * C_, 4 * C_, C_, 1.0f);
}

// round 7
// speedup vs baseline: 7.0805x; 1.0159x over previous
#include <cuda_runtime.h>
#include <cuda_fp16.h>
#include <cstdint>
#include <math.h>

#define B_  8
#define T_  2048
#define C_  512
#define H_  2
#define HS_ 256
#define BT_ (B_ * T_)
#define EPS_ 1e-5f

// ---------------- device scratch (static, allocation-free) ----------------
__device__ __align__(256) __half g_h[BT_ * C_];                       // LN out / attn-out
__device__ __align__(256) __half g_qkv[(size_t)BT_ * 3 * C_];         // [BT, 1536] q|k|v
__device__ __align__(256) float  g_x1[BT_ * C_];                      // residual after attention
__device__ __align__(256) __half g_f1[(size_t)BT_ * 4 * C_];          // FFN intermediate
__device__ __align__(256) __half g_wqkvT[3 * C_ * C_];                // [1536, 512] (Wq pre-scaled)
__device__ __align__(256) __half g_wprojT[C_ * C_];                   // [512, 512]
__device__ __align__(256) __half g_w1T[4 * C_ * C_];                  // [2048, 512]
__device__ __align__(256) __half g_w2T[4 * C_ * C_];                  // [512, 2048]

// ---------------- small PTX helpers ----------------
__device__ __forceinline__ uint32_t su32(const void* p) {
    uint32_t a;
    asm("{ .reg .u64 t; cvta.to.shared.u64 t, %1; cvt.u32.u64 %0, t; }" : "=r"(a) : "l"(p));
    return a;
}
__device__ __forceinline__ void cp16(uint32_t dst, const void* src) {
    asm volatile("cp.async.cg.shared.global [%0], [%1], 16;" :: "r"(dst), "l"(src));
}
__device__ __forceinline__ void ldsm4(uint32_t* r, uint32_t a) {
    asm volatile("ldmatrix.sync.aligned.m8n8.x4.shared.b16 {%0,%1,%2,%3}, [%4];"
                 : "=r"(r[0]), "=r"(r[1]), "=r"(r[2]), "=r"(r[3]) : "r"(a));
}
__device__ __forceinline__ void ldsm4t(uint32_t* r, uint32_t a) {
    asm volatile("ldmatrix.sync.aligned.m8n8.x4.trans.shared.b16 {%0,%1,%2,%3}, [%4];"
                 : "=r"(r[0]), "=r"(r[1]), "=r"(r[2]), "=r"(r[3]) : "r"(a));
}
__device__ __forceinline__ void mma_f16(float* d, const uint32_t* a, uint32_t b0, uint32_t b1) {
    asm volatile(
        "mma.sync.aligned.m16n8k16.row.col.f32.f16.f16.f32 "
        "{%0,%1,%2,%3}, {%4,%5,%6,%7}, {%8,%9}, {%0,%1,%2,%3};"
        : "+f"(d[0]), "+f"(d[1]), "+f"(d[2]), "+f"(d[3])
        : "r"(a[0]), "r"(a[1]), "r"(a[2]), "r"(a[3]), "r"(b0), "r"(b1));
}

// ---------------- weight repacks (transpose + fp16 round) ----------------
// Wq pre-scaled by log2(e)/sqrt(HS) so flash works in base-2 (exp -> exp2).
#define QSCALE_ (0.0625f * 1.4426950408889634f)
__global__ void repack_qkvT(const float* __restrict__ Wq, const float* __restrict__ Wk,
                            const float* __restrict__ Wv) {
    int idx = blockIdx.x * blockDim.x + threadIdx.x;     // [0, 1536*512)
    if (idx >= 3 * C_ * C_) return;
    int n = idx / C_, k = idx % C_;
    int part = n / C_;
    int nn = n % C_;
    int h = nn / HS_, d = nn % HS_;
    const float* W = (part == 0) ? Wq : ((part == 1) ? Wk : Wv);
    float scale = (part == 0) ? QSCALE_ : 1.0f;
    g_wqkvT[idx] = __float2half_rn(W[(size_t)h * C_ * HS_ + (size_t)k * HS_ + d] * scale);
}

// merged transpose of Wproj / W1 / W2 -> fp16, one launch.
// blocks: [0,256) Wproj (512x512), [256,1280) W1 (512x2048), [1280,2304) W2 (2048x512)
__global__ void transpose_all(const float* __restrict__ Wproj, const float* __restrict__ W1,
                              const float* __restrict__ W2) {
    __shared__ float t[32][33];
    int bid = blockIdx.x;
    const float* in;
    __half* out;
    int K, N, tt;
    if (bid < 256)       { in = Wproj; out = g_wprojT; K = 512;  N = 512;  tt = bid; }
    else if (bid < 1280) { in = W1;    out = g_w1T;    K = 512;  N = 2048; tt = bid - 256; }
    else                 { in = W2;    out = g_w2T;    K = 2048; N = 512;  tt = bid - 1280; }
    int ntx = N / 32;
    int n0 = (tt % ntx) * 32, k0 = (tt / ntx) * 32;
    int tx = threadIdx.x, ty = threadIdx.y;  // 32x8
#pragma unroll
    for (int i = 0; i < 32; i += 8)
        t[ty + i][tx] = in[(size_t)(k0 + ty + i) * N + n0 + tx];
    __syncthreads();
#pragma unroll
    for (int i = 0; i < 32; i += 8)
        out[(size_t)(n0 + ty + i) * K + k0 + tx] = __float2half_rn(t[tx][ty + i]);
}

// ---------------- LayerNorm: warp per row, shuffle-only, float4 ----------------
__global__ void ln_kernel(const float* __restrict__ x, const float* __restrict__ g,
                          const float* __restrict__ b, __half* __restrict__ out) {
    const int lane = threadIdx.x & 31, wid = threadIdx.x >> 5;
    const int row = blockIdx.x * 8 + wid;
    const float4* xr = (const float4*)(x + (size_t)row * C_);
    float4 v[4];
    float s = 0.f, ss = 0.f;
#pragma unroll
    for (int i = 0; i < 4; i++) {
        v[i] = xr[i * 32 + lane];
        s  += v[i].x + v[i].y + v[i].z + v[i].w;
        ss += v[i].x * v[i].x + v[i].y * v[i].y + v[i].z * v[i].z + v[i].w * v[i].w;
    }
#pragma unroll
    for (int o = 16; o; o >>= 1) {
        s  += __shfl_xor_sync(0xffffffffu, s, o);
        ss += __shfl_xor_sync(0xffffffffu, ss, o);
    }
    float mean = s * (1.0f / C_);
    float var  = ss * (1.0f / C_) - mean * mean;
    float inv  = rsqrtf(var + EPS_);
    const float4* gg4 = (const float4*)g;
    const float4* bb4 = (const float4*)b;
    uint2* orow = (uint2*)(out + (size_t)row * C_);
#pragma unroll
    for (int i = 0; i < 4; i++) {
        float4 gg = gg4[i * 32 + lane], bb = bb4[i * 32 + lane];
        __half2 h0 = __floats2half2_rn((v[i].x - mean) * inv * gg.x + bb.x,
                                       (v[i].y - mean) * inv * gg.y + bb.y);
        __half2 h1 = __floats2half2_rn((v[i].z - mean) * inv * gg.z + bb.z,
                                       (v[i].w - mean) * inv * gg.w + bb.w);
        uint2 o2;
        o2.x = *(uint32_t*)&h0;
        o2.y = *(uint32_t*)&h1;
        orow[i * 32 + lane] = o2;
    }
}

// ---------------- fused flash attention (base-2 online softmax) ---------------------
#define QT_  128
#define KT_  64
#define SRH  264                       // smem row stride in halves (256 + 8 pad)
#define FLASH_SHM ((QT_ + 4 * KT_) * SRH * 2)   // Q + 2 stages of (K+V) = 202752 B

__global__ void __launch_bounds__(256, 1)
flash_kernel(const __half* __restrict__ qkv, const int* __restrict__ mask,
             __half* __restrict__ outh) {
    extern __shared__ __half sh[];
    const uint32_t sb = su32(sh);
    const int tid = threadIdx.x, lane = tid & 31, wid = tid >> 5;
    const int bh = blockIdx.y, b = bh >> 1, h = bh & 1;
    const int q0 = blockIdx.x * QT_;

    const uint32_t suQ = sb;
    const uint32_t suK0 = sb + (uint32_t)(QT_ * SRH * 2);
    const uint32_t stageB = (uint32_t)(2 * KT_ * SRH * 2);

    // ---- stage Q tile (128 x 256 halves) ----
    const int cc16 = tid & 31, rw = tid >> 5;
    {
        const __half* gq = qkv + ((size_t)(b * T_ + q0) + rw) * 1536 + h * HS_ + cc16 * 8;
        uint32_t dq = suQ + (uint32_t)(rw * SRH + cc16 * 8) * 2;
#pragma unroll
        for (int i = 0; i < 16; i++)
            cp16(dq + (uint32_t)(8 * i * SRH) * 2, gq + (size_t)(8 * i) * 1536);
    }
    const __half* gk = qkv + ((size_t)b * T_) * 1536 + C_ + h * HS_ + cc16 * 8;
    const __half* gv = gk + C_;

    // ---- prologue: kv tile 0 ----
    {
        uint32_t dst = suK0 + (uint32_t)(rw * SRH + cc16 * 8) * 2;
#pragma unroll
        for (int i = 0; i < 8; i++) {
            cp16(dst + (uint32_t)(8 * i * SRH) * 2, gk + (size_t)(rw + 8 * i) * 1536);
            cp16(dst + (uint32_t)((KT_ + 8 * i) * SRH) * 2, gv + (size_t)(rw + 8 * i) * 1536);
        }
    }
    asm volatile("cp.async.commit_group;");

    // fragment base addresses
    const uint32_t aAddr = suQ +
        (uint32_t)(((wid * 16 + (lane & 15)) * SRH) * 2 + (lane >> 4) * 16);
    const uint32_t kBase = suK0 +
        (uint32_t)((((lane & 7) + ((lane >> 4) & 1) * 8) * SRH) * 2 + ((lane >> 3) & 1) * 16);
    const uint32_t vBase = suK0 + (uint32_t)(KT_ * SRH * 2) +
        (uint32_t)((((lane & 7) + ((lane >> 3) & 1) * 8) * SRH) * 2 + (lane >> 4) * 16);

    float o[32][4];
#pragma unroll
    for (int i = 0; i < 32; i++)
#pragma unroll
        for (int c = 0; c < 4; c++) o[i][c] = 0.f;
    float m0 = -1e30f, m1 = -1e30f, l0 = 0.f, l1 = 0.f;

    const int qr = q0 + wid * 16 + (lane >> 2);
    const int* mrow0 = mask + ((size_t)b * T_ + qr) * T_;
    const int* mrow1 = mrow0 + 8 * T_;
    const int cq = 2 * (lane & 3);

    const int NJ = T_ / KT_;   // 32
    for (int j = 0; j < NJ; j++) {
        if (j + 1 < NJ) {
            const int kv1 = (j + 1) * KT_;
            uint32_t dst = suK0 + (uint32_t)((j + 1) & 1) * stageB +
                           (uint32_t)(rw * SRH + cc16 * 8) * 2;
#pragma unroll
            for (int i = 0; i < 8; i++) {
                cp16(dst + (uint32_t)(8 * i * SRH) * 2, gk + (size_t)(kv1 + rw + 8 * i) * 1536);
                cp16(dst + (uint32_t)((KT_ + 8 * i) * SRH) * 2,
                     gv + (size_t)(kv1 + rw + 8 * i) * 1536);
            }
        }
        asm volatile("cp.async.commit_group;");
        asm volatile("cp.async.wait_group 1;");    // tile j (and Q) resident
        __syncthreads();
        const uint32_t soff = (uint32_t)(j & 1) * stageB;

        // ---- S = Q K^T  (16 x 64 per warp) ----
        float s[8][4];
#pragma unroll
        for (int nt = 0; nt < 8; nt++)
#pragma unroll
            for (int c = 0; c < 4; c++) s[nt][c] = 0.f;
#pragma unroll
        for (int ks = 0; ks < 16; ks++) {
            uint32_t aR[4];
            ldsm4(aR, aAddr + ks * 32);
#pragma unroll
            for (int ng = 0; ng < 4; ng++) {
                uint32_t bR[4];
                ldsm4(bR, kBase + soff + (uint32_t)(16 * ng * SRH) * 2 + ks * 32);
                mma_f16(s[2 * ng],     aR, bR[0], bR[1]);
                mma_f16(s[2 * ng + 1], aR, bR[2], bR[3]);
            }
        }

        // ---- mask + online softmax (base-2) ----
        const int kv0 = j * KT_;
        float mx0 = -1e30f, mx1 = -1e30f;
#pragma unroll
        for (int nt = 0; nt < 8; nt++) {
            int col = kv0 + nt * 8 + cq;
            int2 ma = *(const int2*)(mrow0 + col);
            int2 mb = *(const int2*)(mrow1 + col);
            if (ma.x == 0) s[nt][0] = -1e30f;
            if (ma.y == 0) s[nt][1] = -1e30f;
            if (mb.x == 0) s[nt][2] = -1e30f;
            if (mb.y == 0) s[nt][3] = -1e30f;
            mx0 = fmaxf(mx0, fmaxf(s[nt][0], s[nt][1]));
            mx1 = fmaxf(mx1, fmaxf(s[nt][2], s[nt][3]));
        }
        mx0 = fmaxf(mx0, __shfl_xor_sync(0xffffffffu, mx0, 1));
        mx0 = fmaxf(mx0, __shfl_xor_sync(0xffffffffu, mx0, 2));
        mx1 = fmaxf(mx1, __shfl_xor_sync(0xffffffffu, mx1, 1));
        mx1 = fmaxf(mx1, __shfl_xor_sync(0xffffffffu, mx1, 2));
        float mn0 = fmaxf(m0, mx0), mn1 = fmaxf(m1, mx1);
        float al0 = exp2f(m0 - mn0), al1 = exp2f(m1 - mn1);   // ==1.0f when no new max
        m0 = mn0; m1 = mn1;

        float rs0 = 0.f, rs1 = 0.f;
        uint32_t pH[8][2];
#pragma unroll
        for (int nt = 0; nt < 8; nt++) {
            __half2 e01 = h2exp2(__floats2half2_rn(s[nt][0] - mn0, s[nt][1] - mn0));
            __half2 e23 = h2exp2(__floats2half2_rn(s[nt][2] - mn1, s[nt][3] - mn1));
            pH[nt][0] = *(uint32_t*)&e01;
            pH[nt][1] = *(uint32_t*)&e23;
            float2 f01 = __half22float2(e01), f23 = __half22float2(e23);
            rs0 += f01.x + f01.y;
            rs1 += f23.x + f23.y;
        }
        rs0 += __shfl_xor_sync(0xffffffffu, rs0, 1);
        rs0 += __shfl_xor_sync(0xffffffffu, rs0, 2);
        rs1 += __shfl_xor_sync(0xffffffffu, rs1, 1);
        rs1 += __shfl_xor_sync(0xffffffffu, rs1, 2);
        l0 = l0 * al0 + rs0;
        l1 = l1 * al1 + rs1;
        if (__any_sync(0xffffffffu, (al0 != 1.f) | (al1 != 1.f))) {
#pragma unroll
            for (int nt = 0; nt < 32; nt++) {
                o[nt][0] *= al0; o[nt][1] *= al0;
                o[nt][2] *= al1; o[nt][3] *= al1;
            }
        }

        // ---- O += P V ----
#pragma unroll
        for (int ks = 0; ks < 4; ks++) {
            uint32_t aF[4] = { pH[2 * ks][0], pH[2 * ks][1],
                               pH[2 * ks + 1][0], pH[2 * ks + 1][1] };
#pragma unroll
            for (int ng = 0; ng < 16; ng++) {
                uint32_t vR[4];
                ldsm4t(vR, vBase + soff + (uint32_t)(16 * ks * SRH + 16 * ng) * 2);
                mma_f16(o[2 * ng],     aF, vR[0], vR[1]);
                mma_f16(o[2 * ng + 1], aF, vR[2], vR[3]);
            }
        }
        __syncthreads();   // all warps done with buffer before next-iter overwrite
    }

    // ---- finalize + store (concat-head layout) ----
    float i0 = 1.f / l0, i1 = 1.f / l1;
    __half* orow0 = outh + ((size_t)(b * T_) + qr) * C_ + h * HS_;
    __half* orow1 = orow0 + 8 * C_;
#pragma unroll
    for (int nt = 0; nt < 32; nt++) {
        int col = nt * 8 + cq;
        __half2 w0 = __floats2half2_rn(o[nt][0] * i0, o[nt][1] * i0);
        __half2 w1 = __floats2half2_rn(o[nt][2] * i1, o[nt][3] * i1);
        *(__half2*)(orow0 + col) = w0;
        *(__half2*)(orow1 + col) = w1;
    }
}

// ---------------- mma.sync fp16 NT GEMM: 128x128 tile, K=32/stage, 3-stage ---------
// Triple-buffered cp.async -> ONE __syncthreads per K-iter.
#define SROWB  80
#define TILEB  (128 * SROWB)
#define STAGEB (2 * TILEB)          // 20480 B (A tile + B tile)
#define NSTG   3
#define SHMB   (NSTG * STAGEB)      // 61440 B

template <int MODE>
__global__ void __launch_bounds__(128, 2)
mma_gemm(const __half* __restrict__ A, const __half* __restrict__ Bm, void* __restrict__ Cout,
         const float* __restrict__ bias, const float* __restrict__ res,
         int K, int lda, int ldb, int ldc) {
    extern __shared__ char smraw[];
    const uint32_t sbase = su32(smraw);
    const int tid = threadIdx.x, lane = tid & 31, wid = tid >> 5;
    const int wm = wid >> 1, wn = wid & 1;

    const int m0 = blockIdx.y * 128, n0 = blockIdx.x * 128;

    float acc[4][8][4];
#pragma unroll
    for (int i = 0; i < 4; i++)
#pragma unroll
        for (int j = 0; j < 8; j++)
#pragma unroll
            for (int c = 0; c < 4; c++) acc[i][j][c] = 0.f;

    const int c = tid & 3, r0 = tid >> 2;
    const uint32_t dA0 = sbase + (uint32_t)(r0 * SROWB + c * 16);
    const uint32_t dB0 = dA0 + TILEB;
    const __half* gA0 = A  + (size_t)(m0 + r0) * lda + c * 8;
    const __half* gB0 = Bm + (size_t)(n0 + r0) * ldb + c * 8;
    const int nk = K >> 5;

    const uint32_t aF0 = sbase + (uint32_t)((wm * 64 + (lane & 15)) * SROWB + (lane >> 4) * 16);
    const uint32_t bF0 = sbase + TILEB +
        (uint32_t)((wn * 64 + (lane & 7) + ((lane >> 4) & 1) * 8) * SROWB + ((lane >> 3) & 1) * 16);

    // prologue: stages 0 and 1 (separate commit groups)
#pragma unroll
    for (int p = 0; p < 2; p++) {
        if (p < nk) {
            const uint32_t soff = (uint32_t)(p % NSTG) * STAGEB;
            const __half* ga = gA0 + p * 32;
            const __half* gb = gB0 + p * 32;
#pragma unroll
            for (int t = 0; t < 4; t++) {
                cp16(dA0 + soff + (uint32_t)(32 * t * SROWB), ga + (size_t)(32 * t) * lda);
                cp16(dB0 + soff + (uint32_t)(32 * t * SROWB), gb + (size_t)(32 * t) * ldb);
            }
        }
        asm volatile("cp.async.commit_group;");
    }

    for (int j = 0; j < nk; j++) {
        asm volatile("cp.async.wait_group 1;");   // stage j landed (j+1 may be in flight)
        __syncthreads();                          // also: all warps done with buf (j+2)%3

        // issue stage j+2 into buffer (j+2)%3 == (j-1)%3 (consumed before the sync)
        if (j + 2 < nk) {
            const uint32_t soff = (uint32_t)((j + 2) % NSTG) * STAGEB;
            const __half* ga = gA0 + (j + 2) * 32;
            const __half* gb = gB0 + (j + 2) * 32;
#pragma unroll
            for (int t = 0; t < 4; t++) {
                cp16(dA0 + soff + (uint32_t)(32 * t * SROWB), ga + (size_t)(32 * t) * lda);
                cp16(dB0 + soff + (uint32_t)(32 * t * SROWB), gb + (size_t)(32 * t) * ldb);
            }
        }
        asm volatile("cp.async.commit_group;");

        const uint32_t sa = aF0 + (uint32_t)(j % NSTG) * STAGEB;
        const uint32_t sb = bF0 + (uint32_t)(j % NSTG) * STAGEB;
#pragma unroll
        for (int ks = 0; ks < 2; ks++) {
            uint32_t aR[4][4], bR[4][4];
#pragma unroll
            for (int mt = 0; mt < 4; mt++)
                ldsm4(aR[mt], sa + (uint32_t)(mt * 16 * SROWB + ks * 32));
#pragma unroll
            for (int np = 0; np < 4; np++)
                ldsm4(bR[np], sb + (uint32_t)(np * 16 * SROWB + ks * 32));
#pragma unroll
            for (int mt = 0; mt < 4; mt++)
#pragma unroll
                for (int nt = 0; nt < 8; nt++)
                    mma_f16(acc[mt][nt], aR[mt],
                            bR[nt >> 1][(nt & 1) * 2], bR[nt >> 1][(nt & 1) * 2 + 1]);
        }
    }

    const int r = lane >> 2, cq = 2 * (lane & 3);
#pragma unroll
    for (int mt = 0; mt < 4; mt++) {
        const int row0 = m0 + wm * 64 + mt * 16 + r;
#pragma unroll
        for (int nt = 0; nt < 8; nt++) {
            const int col = n0 + wn * 64 + nt * 8 + cq;
            float v0 = acc[mt][nt][0], v1 = acc[mt][nt][1];
            float v2 = acc[mt][nt][2], v3 = acc[mt][nt][3];
            if (MODE == 1) {
                float* Cm = (float*)Cout;
                float b0 = bias[col], b1 = bias[col + 1];
                const float* r0p = res + (size_t)row0 * ldc + col;
                const float* r1p = res + (size_t)(row0 + 8) * ldc + col;
                float2 o0, o1;
                o0.x = v0 + b0 + r0p[0]; o0.y = v1 + b1 + r0p[1];
                o1.x = v2 + b0 + r1p[0]; o1.y = v3 + b1 + r1p[1];
                *(float2*)(Cm + (size_t)row0 * ldc + col) = o0;
                *(float2*)(Cm + (size_t)(row0 + 8) * ldc + col) = o1;
            } else {
                __half* Cm = (__half*)Cout;
                __half2 h0, h1;
                if (MODE == 2) {
                    float b0 = bias[col], b1 = bias[col + 1];
                    h0 = __floats2half2_rn(fmaxf(v0 + b0, 0.f), fmaxf(v1 + b1, 0.f));
                    h1 = __floats2half2_rn(fmaxf(v2 + b0, 0.f), fmaxf(v3 + b1, 0.f));
                } else {
                    h0 = __floats2half2_rn(v0, v1);
                    h1 = __floats2half2_rn(v2, v3);
                }
                *(__half2*)(Cm + (size_t)row0 * ldc + col) = h0;
                *(__half2*)(Cm + (size_t)(row0 + 8) * ldc + col) = h1;
            }
        }
    }
}

// ---------------- host launcher ----------------
extern "C" void kernel_launch(void* const* d_in, const int* in_sizes, int n_in,
                              void* d_out, int out_size) {
    const float* x     = (const float*)d_in[0];
    const int*   smask = (const int*)d_in[1];
    const float* Wq    = (const float*)d_in[2];
    const float* Wk    = (const float*)d_in[3];
    const float* Wv    = (const float*)d_in[4];
    const float* Wproj = (const float*)d_in[5];
    const float* bproj = (const float*)d_in[6];
    const float* W1    = (const float*)d_in[7];
    const float* b1    = (const float*)d_in[8];
    const float* W2    = (const float*)d_in[9];
    const float* b2    = (const float*)d_in[10];
    const float* g1    = (const float*)d_in[11];
    const float* be1   = (const float*)d_in[12];
    const float* g2    = (const float*)d_in[13];
    const float* be2   = (const float*)d_in[14];
    float* out = (float*)d_out;

    __half *pH, *pQKV, *pF1, *pWqkvT, *pWprojT, *pW1T, *pW2T;
    float* pX1;
    cudaGetSymbolAddress((void**)&pH,      g_h);
    cudaGetSymbolAddress((void**)&pQKV,    g_qkv);
    cudaGetSymbolAddress((void**)&pX1,     g_x1);
    cudaGetSymbolAddress((void**)&pF1,     g_f1);
    cudaGetSymbolAddress((void**)&pWqkvT,  g_wqkvT);
    cudaGetSymbolAddress((void**)&pWprojT, g_wprojT);
    cudaGetSymbolAddress((void**)&pW1T,    g_w1T);
    cudaGetSymbolAddress((void**)&pW2T,    g_w2T);

    cudaFuncSetAttribute(mma_gemm<1>, cudaFuncAttributeMaxDynamicSharedMemorySize, SHMB);
    cudaFuncSetAttribute(mma_gemm<2>, cudaFuncAttributeMaxDynamicSharedMemorySize, SHMB);
    cudaFuncSetAttribute(mma_gemm<3>, cudaFuncAttributeMaxDynamicSharedMemorySize, SHMB);
    cudaFuncSetAttribute(flash_kernel, cudaFuncAttributeMaxDynamicSharedMemorySize, FLASH_SHM);
    dim3 blk(128);

    // weight repacks (rounded to fp16; Wq pre-scaled log2e/16)
    repack_qkvT<<<(3 * C_ * C_ + 255) / 256, 256>>>(Wq, Wk, Wv);
    transpose_all<<<2304, dim3(32, 8)>>>(Wproj, W1, W2);

    // LN1
    ln_kernel<<<BT_ / 8, 256>>>(x, g1, be1, pH);

    // QKV fused: [BT,512] x [1536,512]^T -> [BT,1536]
    mma_gemm<3><<<dim3(12, 128, 1), blk, SHMB>>>(pH, pWqkvT, pQKV, nullptr, nullptr,
        C_, C_, C_, 3 * C_);

    // fused flash attention -> pH (concat-head fp16)
    flash_kernel<<<dim3(T_ / QT_, B_ * H_), 256, FLASH_SHM>>>(pQKV, smask, pH);

    // x1 = x + o @ Wproj + bproj
    mma_gemm<1><<<dim3(4, 128, 1), blk, SHMB>>>(pH, pWprojT, pX1, bproj, x,
        C_, C_, C_, C_);

    // LN2
    ln_kernel<<<BT_ / 8, 256>>>(pX1, g2, be2, pH);

    // f1 = relu(h2 @ W1 + b1)
    mma_gemm<2><<<dim3(16, 128, 1), blk, SHMB>>>(pH, pW1T, pF1, b1, nullptr,
        C_, C_, C_, 4 * C_);

    // out = x1 + f1 @ W2 + b2
    mma_gemm<1><<<dim3(4, 128, 1), blk, SHMB>>>(pF1, pW2T, out, b2, pX1,
        4 * C_, 4 * C_, 4 * C_, C_);
}

// round 8
// speedup vs baseline: 7.1399x; 1.0084x over previous
#include <cuda_runtime.h>
#include <cuda_fp16.h>
#include <cstdint>
#include <math.h>

#define B_  8
#define T_  2048
#define C_  512
#define H_  2
#define HS_ 256
#define BT_ (B_ * T_)
#define EPS_ 1e-5f

// ---------------- device scratch (static, allocation-free) ----------------
__device__ __align__(256) __half g_h[BT_ * C_];                       // LN out / attn-out
__device__ __align__(256) __half g_qkv[(size_t)BT_ * 3 * C_];         // [BT, 1536] q|k|v
__device__ __align__(256) float  g_x1[BT_ * C_];                      // residual after attention
__device__ __align__(256) __half g_f1[(size_t)BT_ * 4 * C_];          // FFN intermediate
__device__ __align__(256) __half g_wqkvT[3 * C_ * C_];                // [1536, 512] (Wq pre-scaled)
__device__ __align__(256) __half g_wprojT[C_ * C_];                   // [512, 512]
__device__ __align__(256) __half g_w1T[4 * C_ * C_];                  // [2048, 512]
__device__ __align__(256) __half g_w2T[4 * C_ * C_];                  // [512, 2048]

// ---------------- small PTX helpers ----------------
__device__ __forceinline__ uint32_t su32(const void* p) {
    uint32_t a;
    asm("{ .reg .u64 t; cvta.to.shared.u64 t, %1; cvt.u32.u64 %0, t; }" : "=r"(a) : "l"(p));
    return a;
}
__device__ __forceinline__ void cp16(uint32_t dst, const void* src) {
    asm volatile("cp.async.cg.shared.global [%0], [%1], 16;" :: "r"(dst), "l"(src));
}
__device__ __forceinline__ void ldsm4(uint32_t* r, uint32_t a) {
    asm volatile("ldmatrix.sync.aligned.m8n8.x4.shared.b16 {%0,%1,%2,%3}, [%4];"
                 : "=r"(r[0]), "=r"(r[1]), "=r"(r[2]), "=r"(r[3]) : "r"(a));
}
__device__ __forceinline__ void ldsm4t(uint32_t* r, uint32_t a) {
    asm volatile("ldmatrix.sync.aligned.m8n8.x4.trans.shared.b16 {%0,%1,%2,%3}, [%4];"
                 : "=r"(r[0]), "=r"(r[1]), "=r"(r[2]), "=r"(r[3]) : "r"(a));
}
__device__ __forceinline__ void mma_f16(float* d, const uint32_t* a, uint32_t b0, uint32_t b1) {
    asm volatile(
        "mma.sync.aligned.m16n8k16.row.col.f32.f16.f16.f32 "
        "{%0,%1,%2,%3}, {%4,%5,%6,%7}, {%8,%9}, {%0,%1,%2,%3};"
        : "+f"(d[0]), "+f"(d[1]), "+f"(d[2]), "+f"(d[3])
        : "r"(a[0]), "r"(a[1]), "r"(a[2]), "r"(a[3]), "r"(b0), "r"(b1));
}

// ---------------- weight repacks (transpose + fp16 round) ----------------
// Wq pre-scaled by log2(e)/sqrt(HS) so flash works in base-2 (exp -> exp2).
#define QSCALE_ (0.0625f * 1.4426950408889634f)
__global__ void repack_qkvT(const float* __restrict__ Wq, const float* __restrict__ Wk,
                            const float* __restrict__ Wv) {
    int idx = blockIdx.x * blockDim.x + threadIdx.x;     // [0, 1536*512)
    if (idx >= 3 * C_ * C_) return;
    int n = idx / C_, k = idx % C_;
    int part = n / C_;
    int nn = n % C_;
    int h = nn / HS_, d = nn % HS_;
    const float* W = (part == 0) ? Wq : ((part == 1) ? Wk : Wv);
    float scale = (part == 0) ? QSCALE_ : 1.0f;
    g_wqkvT[idx] = __float2half_rn(W[(size_t)h * C_ * HS_ + (size_t)k * HS_ + d] * scale);
}

// merged transpose of Wproj / W1 / W2 -> fp16, one launch.
__global__ void transpose_all(const float* __restrict__ Wproj, const float* __restrict__ W1,
                              const float* __restrict__ W2) {
    __shared__ float t[32][33];
    int bid = blockIdx.x;
    const float* in;
    __half* out;
    int K, N, tt;
    if (bid < 256)       { in = Wproj; out = g_wprojT; K = 512;  N = 512;  tt = bid; }
    else if (bid < 1280) { in = W1;    out = g_w1T;    K = 512;  N = 2048; tt = bid - 256; }
    else                 { in = W2;    out = g_w2T;    K = 2048; N = 512;  tt = bid - 1280; }
    int ntx = N / 32;
    int n0 = (tt % ntx) * 32, k0 = (tt / ntx) * 32;
    int tx = threadIdx.x, ty = threadIdx.y;  // 32x8
#pragma unroll
    for (int i = 0; i < 32; i += 8)
        t[ty + i][tx] = in[(size_t)(k0 + ty + i) * N + n0 + tx];
    __syncthreads();
#pragma unroll
    for (int i = 0; i < 32; i += 8)
        out[(size_t)(n0 + ty + i) * K + k0 + tx] = __float2half_rn(t[tx][ty + i]);
}

// ---------------- LayerNorm: warp per row, shuffle-only, float4 ----------------
__global__ void ln_kernel(const float* __restrict__ x, const float* __restrict__ g,
                          const float* __restrict__ b, __half* __restrict__ out) {
    const int lane = threadIdx.x & 31, wid = threadIdx.x >> 5;
    const int row = blockIdx.x * 8 + wid;
    const float4* xr = (const float4*)(x + (size_t)row * C_);
    float4 v[4];
    float s = 0.f, ss = 0.f;
#pragma unroll
    for (int i = 0; i < 4; i++) {
        v[i] = xr[i * 32 + lane];
        s  += v[i].x + v[i].y + v[i].z + v[i].w;
        ss += v[i].x * v[i].x + v[i].y * v[i].y + v[i].z * v[i].z + v[i].w * v[i].w;
    }
#pragma unroll
    for (int o = 16; o; o >>= 1) {
        s  += __shfl_xor_sync(0xffffffffu, s, o);
        ss += __shfl_xor_sync(0xffffffffu, ss, o);
    }
    float mean = s * (1.0f / C_);
    float var  = ss * (1.0f / C_) - mean * mean;
    float inv  = rsqrtf(var + EPS_);
    const float4* gg4 = (const float4*)g;
    const float4* bb4 = (const float4*)b;
    uint2* orow = (uint2*)(out + (size_t)row * C_);
#pragma unroll
    for (int i = 0; i < 4; i++) {
        float4 gg = gg4[i * 32 + lane], bb = bb4[i * 32 + lane];
        __half2 h0 = __floats2half2_rn((v[i].x - mean) * inv * gg.x + bb.x,
                                       (v[i].y - mean) * inv * gg.y + bb.y);
        __half2 h1 = __floats2half2_rn((v[i].z - mean) * inv * gg.z + bb.z,
                                       (v[i].w - mean) * inv * gg.w + bb.w);
        uint2 o2;
        o2.x = *(uint32_t*)&h0;
        o2.y = *(uint32_t*)&h1;
        orow[i * 32 + lane] = o2;
    }
}

// ---------------- fused flash attention (base-2 online softmax) ---------------------
#define QT_  128
#define KT_  64
#define SRH  264                       // smem row stride in halves (256 + 8 pad)
#define FLASH_SHM ((QT_ + 4 * KT_) * SRH * 2)   // Q + 2 stages of (K+V) = 202752 B

__global__ void __launch_bounds__(256, 1)
flash_kernel(const __half* __restrict__ qkv, const int* __restrict__ mask,
             __half* __restrict__ outh) {
    extern __shared__ __half sh[];
    const uint32_t sb = su32(sh);
    const int tid = threadIdx.x, lane = tid & 31, wid = tid >> 5;
    const int bh = blockIdx.y, b = bh >> 1, h = bh & 1;
    const int q0 = blockIdx.x * QT_;

    const uint32_t suQ = sb;
    const uint32_t suK0 = sb + (uint32_t)(QT_ * SRH * 2);
    const uint32_t stageB = (uint32_t)(2 * KT_ * SRH * 2);

    // ---- stage Q tile (128 x 256 halves) ----
    const int cc16 = tid & 31, rw = tid >> 5;
    {
        const __half* gq = qkv + ((size_t)(b * T_ + q0) + rw) * 1536 + h * HS_ + cc16 * 8;
        uint32_t dq = suQ + (uint32_t)(rw * SRH + cc16 * 8) * 2;
#pragma unroll
        for (int i = 0; i < 16; i++)
            cp16(dq + (uint32_t)(8 * i * SRH) * 2, gq + (size_t)(8 * i) * 1536);
    }
    const __half* gk = qkv + ((size_t)b * T_) * 1536 + C_ + h * HS_ + cc16 * 8;
    const __half* gv = gk + C_;

    // ---- prologue: kv tile 0 ----
    {
        uint32_t dst = suK0 + (uint32_t)(rw * SRH + cc16 * 8) * 2;
#pragma unroll
        for (int i = 0; i < 8; i++) {
            cp16(dst + (uint32_t)(8 * i * SRH) * 2, gk + (size_t)(rw + 8 * i) * 1536);
            cp16(dst + (uint32_t)((KT_ + 8 * i) * SRH) * 2, gv + (size_t)(rw + 8 * i) * 1536);
        }
    }
    asm volatile("cp.async.commit_group;");

    // fragment base addresses
    const uint32_t aAddr = suQ +
        (uint32_t)(((wid * 16 + (lane & 15)) * SRH) * 2 + (lane >> 4) * 16);
    const uint32_t kBase = suK0 +
        (uint32_t)((((lane & 7) + ((lane >> 4) & 1) * 8) * SRH) * 2 + ((lane >> 3) & 1) * 16);
    const uint32_t vBase = suK0 + (uint32_t)(KT_ * SRH * 2) +
        (uint32_t)((((lane & 7) + ((lane >> 3) & 1) * 8) * SRH) * 2 + (lane >> 4) * 16);

    float o[32][4];
#pragma unroll
    for (int i = 0; i < 32; i++)
#pragma unroll
        for (int c = 0; c < 4; c++) o[i][c] = 0.f;
    float m0 = -1e30f, m1 = -1e30f, l0 = 0.f, l1 = 0.f;

    const int qr = q0 + wid * 16 + (lane >> 2);
    const int* mrow0 = mask + ((size_t)b * T_ + qr) * T_;
    const int* mrow1 = mrow0 + 8 * T_;
    const int cq = 2 * (lane & 3);

    const int NJ = T_ / KT_;   // 32
    for (int j = 0; j < NJ; j++) {
        if (j + 1 < NJ) {
            const int kv1 = (j + 1) * KT_;
            uint32_t dst = suK0 + (uint32_t)((j + 1) & 1) * stageB +
                           (uint32_t)(rw * SRH + cc16 * 8) * 2;
#pragma unroll
            for (int i = 0; i < 8; i++) {
                cp16(dst + (uint32_t)(8 * i * SRH) * 2, gk + (size_t)(kv1 + rw + 8 * i) * 1536);
                cp16(dst + (uint32_t)((KT_ + 8 * i) * SRH) * 2,
                     gv + (size_t)(kv1 + rw + 8 * i) * 1536);
            }
        }
        asm volatile("cp.async.commit_group;");
        asm volatile("cp.async.wait_group 1;");    // tile j (and Q) resident
        __syncthreads();
        const uint32_t soff = (uint32_t)(j & 1) * stageB;

        // ---- S = Q K^T  (16 x 64 per warp) ----
        float s[8][4];
#pragma unroll
        for (int nt = 0; nt < 8; nt++)
#pragma unroll
            for (int c = 0; c < 4; c++) s[nt][c] = 0.f;
#pragma unroll
        for (int ks = 0; ks < 16; ks++) {
            uint32_t aR[4];
            ldsm4(aR, aAddr + ks * 32);
#pragma unroll
            for (int ng = 0; ng < 4; ng++) {
                uint32_t bR[4];
                ldsm4(bR, kBase + soff + (uint32_t)(16 * ng * SRH) * 2 + ks * 32);
                mma_f16(s[2 * ng],     aR, bR[0], bR[1]);
                mma_f16(s[2 * ng + 1], aR, bR[2], bR[3]);
            }
        }

        // ---- mask + online softmax (base-2) ----
        const int kv0 = j * KT_;
        float mx0 = -1e30f, mx1 = -1e30f;
#pragma unroll
        for (int nt = 0; nt < 8; nt++) {
            int col = kv0 + nt * 8 + cq;
            int2 ma = *(const int2*)(mrow0 + col);
            int2 mb = *(const int2*)(mrow1 + col);
            if (ma.x == 0) s[nt][0] = -1e30f;
            if (ma.y == 0) s[nt][1] = -1e30f;
            if (mb.x == 0) s[nt][2] = -1e30f;
            if (mb.y == 0) s[nt][3] = -1e30f;
            mx0 = fmaxf(mx0, fmaxf(s[nt][0], s[nt][1]));
            mx1 = fmaxf(mx1, fmaxf(s[nt][2], s[nt][3]));
        }
        mx0 = fmaxf(mx0, __shfl_xor_sync(0xffffffffu, mx0, 1));
        mx0 = fmaxf(mx0, __shfl_xor_sync(0xffffffffu, mx0, 2));
        mx1 = fmaxf(mx1, __shfl_xor_sync(0xffffffffu, mx1, 1));
        mx1 = fmaxf(mx1, __shfl_xor_sync(0xffffffffu, mx1, 2));
        float mn0 = fmaxf(m0, mx0), mn1 = fmaxf(m1, mx1);
        float al0 = exp2f(m0 - mn0), al1 = exp2f(m1 - mn1);   // ==1.0f when no new max
        m0 = mn0; m1 = mn1;

        float rs0 = 0.f, rs1 = 0.f;
        uint32_t pH[8][2];
#pragma unroll
        for (int nt = 0; nt < 8; nt++) {
            __half2 e01 = h2exp2(__floats2half2_rn(s[nt][0] - mn0, s[nt][1] - mn0));
            __half2 e23 = h2exp2(__floats2half2_rn(s[nt][2] - mn1, s[nt][3] - mn1));
            pH[nt][0] = *(uint32_t*)&e01;
            pH[nt][1] = *(uint32_t*)&e23;
            float2 f01 = __half22float2(e01), f23 = __half22float2(e23);
            rs0 += f01.x + f01.y;
            rs1 += f23.x + f23.y;
        }
        rs0 += __shfl_xor_sync(0xffffffffu, rs0, 1);
        rs0 += __shfl_xor_sync(0xffffffffu, rs0, 2);
        rs1 += __shfl_xor_sync(0xffffffffu, rs1, 1);
        rs1 += __shfl_xor_sync(0xffffffffu, rs1, 2);
        l0 = l0 * al0 + rs0;
        l1 = l1 * al1 + rs1;
        if (__any_sync(0xffffffffu, (al0 != 1.f) | (al1 != 1.f))) {
#pragma unroll
            for (int nt = 0; nt < 32; nt++) {
                o[nt][0] *= al0; o[nt][1] *= al0;
                o[nt][2] *= al1; o[nt][3] *= al1;
            }
        }

        // ---- O += P V ----
#pragma unroll
        for (int ks = 0; ks < 4; ks++) {
            uint32_t aF[4] = { pH[2 * ks][0], pH[2 * ks][1],
                               pH[2 * ks + 1][0], pH[2 * ks + 1][1] };
#pragma unroll
            for (int ng = 0; ng < 16; ng++) {
                uint32_t vR[4];
                ldsm4t(vR, vBase + soff + (uint32_t)(16 * ks * SRH + 16 * ng) * 2);
                mma_f16(o[2 * ng],     aF, vR[0], vR[1]);
                mma_f16(o[2 * ng + 1], aF, vR[2], vR[3]);
            }
        }
        __syncthreads();   // all warps done with buffer before next-iter overwrite
    }

    // ---- finalize + store (concat-head layout) ----
    float i0 = 1.f / l0, i1 = 1.f / l1;
    __half* orow0 = outh + ((size_t)(b * T_) + qr) * C_ + h * HS_;
    __half* orow1 = orow0 + 8 * C_;
#pragma unroll
    for (int nt = 0; nt < 32; nt++) {
        int col = nt * 8 + cq;
        __half2 w0 = __floats2half2_rn(o[nt][0] * i0, o[nt][1] * i0);
        __half2 w1 = __floats2half2_rn(o[nt][2] * i1, o[nt][3] * i1);
        *(__half2*)(orow0 + col) = w0;
        *(__half2*)(orow1 + col) = w1;
    }
}

// ---------------- mma.sync fp16 NT GEMM: 128x128 tile, 256 thr, 8 warps ------------
// Warp tile 32x64 (wm in 0..3, wn in 0..1). 3-stage cp.async, one sync/iter.
// 2 CTAs/SM (regs capped 128) -> 16 warps/SM for latency hiding.
#define SROWB  80
#define TILEB  (128 * SROWB)
#define STAGEB (2 * TILEB)          // 20480 B (A tile + B tile)
#define NSTG   3
#define SHMB   (NSTG * STAGEB)      // 61440 B

template <int MODE>
__global__ void __launch_bounds__(256, 2)
mma_gemm(const __half* __restrict__ A, const __half* __restrict__ Bm, void* __restrict__ Cout,
         const float* __restrict__ bias, const float* __restrict__ res,
         int K, int lda, int ldb, int ldc) {
    extern __shared__ char smraw[];
    const uint32_t sbase = su32(smraw);
    const int tid = threadIdx.x, lane = tid & 31, wid = tid >> 5;
    const int wm = wid >> 1, wn = wid & 1;   // 4 x 2 warp grid

    const int m0 = blockIdx.y * 128, n0 = blockIdx.x * 128;

    float acc[2][8][4];
#pragma unroll
    for (int i = 0; i < 2; i++)
#pragma unroll
        for (int j = 0; j < 8; j++)
#pragma unroll
            for (int c = 0; c < 4; c++) acc[i][j][c] = 0.f;

    // gmem->smem: thread owns 16B chunk c of row r0 and r0+64
    const int c = tid & 3, r0 = tid >> 2;
    const uint32_t dA0 = sbase + (uint32_t)(r0 * SROWB + c * 16);
    const uint32_t dB0 = dA0 + TILEB;
    const __half* gA0 = A  + (size_t)(m0 + r0) * lda + c * 8;
    const __half* gB0 = Bm + (size_t)(n0 + r0) * ldb + c * 8;
    const int nk = K >> 5;

    const uint32_t aF0 = sbase + (uint32_t)((wm * 32 + (lane & 15)) * SROWB + (lane >> 4) * 16);
    const uint32_t bF0 = sbase + TILEB +
        (uint32_t)((wn * 64 + (lane & 7) + ((lane >> 4) & 1) * 8) * SROWB + ((lane >> 3) & 1) * 16);

    // prologue: stages 0 and 1 (separate commit groups)
#pragma unroll
    for (int p = 0; p < 2; p++) {
        if (p < nk) {
            const uint32_t soff = (uint32_t)(p % NSTG) * STAGEB;
            const __half* ga = gA0 + p * 32;
            const __half* gb = gB0 + p * 32;
#pragma unroll
            for (int t = 0; t < 2; t++) {
                cp16(dA0 + soff + (uint32_t)(64 * t * SROWB), ga + (size_t)(64 * t) * lda);
                cp16(dB0 + soff + (uint32_t)(64 * t * SROWB), gb + (size_t)(64 * t) * ldb);
            }
        }
        asm volatile("cp.async.commit_group;");
    }

    for (int j = 0; j < nk; j++) {
        asm volatile("cp.async.wait_group 1;");   // stage j landed (j+1 may be in flight)
        __syncthreads();                          // all warps done with buf (j+2)%3

        if (j + 2 < nk) {
            const uint32_t soff = (uint32_t)((j + 2) % NSTG) * STAGEB;
            const __half* ga = gA0 + (j + 2) * 32;
            const __half* gb = gB0 + (j + 2) * 32;
#pragma unroll
            for (int t = 0; t < 2; t++) {
                cp16(dA0 + soff + (uint32_t)(64 * t * SROWB), ga + (size_t)(64 * t) * lda);
                cp16(dB0 + soff + (uint32_t)(64 * t * SROWB), gb + (size_t)(64 * t) * ldb);
            }
        }
        asm volatile("cp.async.commit_group;");

        const uint32_t sa = aF0 + (uint32_t)(j % NSTG) * STAGEB;
        const uint32_t sb = bF0 + (uint32_t)(j % NSTG) * STAGEB;
#pragma unroll
        for (int ks = 0; ks < 2; ks++) {
            uint32_t aR[2][4], bR[4][4];
#pragma unroll
            for (int mt = 0; mt < 2; mt++)
                ldsm4(aR[mt], sa + (uint32_t)(mt * 16 * SROWB + ks * 32));
#pragma unroll
            for (int np = 0; np < 4; np++)
                ldsm4(bR[np], sb + (uint32_t)(np * 16 * SROWB + ks * 32));
#pragma unroll
            for (int mt = 0; mt < 2; mt++)
#pragma unroll
                for (int nt = 0; nt < 8; nt++)
                    mma_f16(acc[mt][nt], aR[mt],
                            bR[nt >> 1][(nt & 1) * 2], bR[nt >> 1][(nt & 1) * 2 + 1]);
        }
    }

    const int r = lane >> 2, cq = 2 * (lane & 3);
#pragma unroll
    for (int mt = 0; mt < 2; mt++) {
        const int row0 = m0 + wm * 32 + mt * 16 + r;
#pragma unroll
        for (int nt = 0; nt < 8; nt++) {
            const int col = n0 + wn * 64 + nt * 8 + cq;
            float v0 = acc[mt][nt][0], v1 = acc[mt][nt][1];
            float v2 = acc[mt][nt][2], v3 = acc[mt][nt][3];
            if (MODE == 1) {
                float* Cm = (float*)Cout;
                float b0 = bias[col], b1 = bias[col + 1];
                const float* r0p = res + (size_t)row0 * ldc + col;
                const float* r1p = res + (size_t)(row0 + 8) * ldc + col;
                float2 o0, o1;
                o0.x = v0 + b0 + r0p[0]; o0.y = v1 + b1 + r0p[1];
                o1.x = v2 + b0 + r1p[0]; o1.y = v3 + b1 + r1p[1];
                *(float2*)(Cm + (size_t)row0 * ldc + col) = o0;
                *(float2*)(Cm + (size_t)(row0 + 8) * ldc + col) = o1;
            } else {
                __half* Cm = (__half*)Cout;
                __half2 h0, h1;
                if (MODE == 2) {
                    float b0 = bias[col], b1 = bias[col + 1];
                    h0 = __floats2half2_rn(fmaxf(v0 + b0, 0.f), fmaxf(v1 + b1, 0.f));
                    h1 = __floats2half2_rn(fmaxf(v2 + b0, 0.f), fmaxf(v3 + b1, 0.f));
                } else {
                    h0 = __floats2half2_rn(v0, v1);
                    h1 = __floats2half2_rn(v2, v3);
                }
                *(__half2*)(Cm + (size_t)row0 * ldc + col) = h0;
                *(__half2*)(Cm + (size_t)(row0 + 8) * ldc + col) = h1;
            }
        }
    }
}

// ---------------- host launcher ----------------
extern "C" void kernel_launch(void* const* d_in, const int* in_sizes, int n_in,
                              void* d_out, int out_size) {
    const float* x     = (const float*)d_in[0];
    const int*   smask = (const int*)d_in[1];
    const float* Wq    = (const float*)d_in[2];
    const float* Wk    = (const float*)d_in[3];
    const float* Wv    = (const float*)d_in[4];
    const float* Wproj = (const float*)d_in[5];
    const float* bproj = (const float*)d_in[6];
    const float* W1    = (const float*)d_in[7];
    const float* b1    = (const float*)d_in[8];
    const float* W2    = (const float*)d_in[9];
    const float* b2    = (const float*)d_in[10];
    const float* g1    = (const float*)d_in[11];
    const float* be1   = (const float*)d_in[12];
    const float* g2    = (const float*)d_in[13];
    const float* be2   = (const float*)d_in[14];
    float* out = (float*)d_out;

    __half *pH, *pQKV, *pF1, *pWqkvT, *pWprojT, *pW1T, *pW2T;
    float* pX1;
    cudaGetSymbolAddress((void**)&pH,      g_h);
    cudaGetSymbolAddress((void**)&pQKV,    g_qkv);
    cudaGetSymbolAddress((void**)&pX1,     g_x1);
    cudaGetSymbolAddress((void**)&pF1,     g_f1);
    cudaGetSymbolAddress((void**)&pWqkvT,  g_wqkvT);
    cudaGetSymbolAddress((void**)&pWprojT, g_wprojT);
    cudaGetSymbolAddress((void**)&pW1T,    g_w1T);
    cudaGetSymbolAddress((void**)&pW2T,    g_w2T);

    cudaFuncSetAttribute(mma_gemm<1>, cudaFuncAttributeMaxDynamicSharedMemorySize, SHMB);
    cudaFuncSetAttribute(mma_gemm<2>, cudaFuncAttributeMaxDynamicSharedMemorySize, SHMB);
    cudaFuncSetAttribute(mma_gemm<3>, cudaFuncAttributeMaxDynamicSharedMemorySize, SHMB);
    cudaFuncSetAttribute(flash_kernel, cudaFuncAttributeMaxDynamicSharedMemorySize, FLASH_SHM);
    dim3 blk(256);

    // weight repacks (rounded to fp16; Wq pre-scaled log2e/16)
    repack_qkvT<<<(3 * C_ * C_ + 255) / 256, 256>>>(Wq, Wk, Wv);
    transpose_all<<<2304, dim3(32, 8)>>>(Wproj, W1, W2);

    // LN1
    ln_kernel<<<BT_ / 8, 256>>>(x, g1, be1, pH);

    // QKV fused: [BT,512] x [1536,512]^T -> [BT,1536]
    mma_gemm<3><<<dim3(12, 128, 1), blk, SHMB>>>(pH, pWqkvT, pQKV, nullptr, nullptr,
        C_, C_, C_, 3 * C_);

    // fused flash attention -> pH (concat-head fp16)
    flash_kernel<<<dim3(T_ / QT_, B_ * H_), 256, FLASH_SHM>>>(pQKV, smask, pH);

    // x1 = x + o @ Wproj + bproj
    mma_gemm<1><<<dim3(4, 128, 1), blk, SHMB>>>(pH, pWprojT, pX1, bproj, x,
        C_, C_, C_, C_);

    // LN2
    ln_kernel<<<BT_ / 8, 256>>>(pX1, g2, be2, pH);

    // f1 = relu(h2 @ W1 + b1)
    mma_gemm<2><<<dim3(16, 128, 1), blk, SHMB>>>(pH, pW1T, pF1, b1, nullptr,
        C_, C_, C_, 4 * C_);

    // out = x1 + f1 @ W2 + b2
    mma_gemm<1><<<dim3(4, 128, 1), blk, SHMB>>>(pF1, pW2T, out, b2, pX1,
        4 * C_, 4 * C_, 4 * C_, C_);
}

// round 9
// speedup vs baseline: 7.3093x; 1.0237x over previous
#include <cuda_runtime.h>
#include <cuda_fp16.h>
#include <cstdint>
#include <math.h>

#define B_  8
#define T_  2048
#define C_  512
#define H_  2
#define HS_ 256
#define BT_ (B_ * T_)
#define EPS_ 1e-5f

// ---------------- device scratch (static, allocation-free) ----------------
__device__ __align__(256) __half g_h[BT_ * C_];                       // LN out / attn-out
__device__ __align__(256) __half g_qkv[(size_t)BT_ * 3 * C_];         // [BT, 1536] q|k|v
__device__ __align__(256) float  g_x1[BT_ * C_];                      // residual after attention
__device__ __align__(256) __half g_f1[(size_t)BT_ * 4 * C_];          // FFN intermediate
__device__ __align__(256) __half g_wqkvT[3 * C_ * C_];                // [1536, 512] (Wq pre-scaled)
__device__ __align__(256) __half g_wprojT[C_ * C_];                   // [512, 512]
__device__ __align__(256) __half g_w1T[4 * C_ * C_];                  // [2048, 512]
__device__ __align__(256) __half g_w2T[4 * C_ * C_];                  // [512, 2048]

// ---------------- small PTX helpers ----------------
__device__ __forceinline__ uint32_t su32(const void* p) {
    uint32_t a;
    asm("{ .reg .u64 t; cvta.to.shared.u64 t, %1; cvt.u32.u64 %0, t; }" : "=r"(a) : "l"(p));
    return a;
}
__device__ __forceinline__ void cp16(uint32_t dst, const void* src) {
    asm volatile("cp.async.cg.shared.global [%0], [%1], 16;" :: "r"(dst), "l"(src));
}
__device__ __forceinline__ void ldsm4(uint32_t* r, uint32_t a) {
    asm volatile("ldmatrix.sync.aligned.m8n8.x4.shared.b16 {%0,%1,%2,%3}, [%4];"
                 : "=r"(r[0]), "=r"(r[1]), "=r"(r[2]), "=r"(r[3]) : "r"(a));
}
__device__ __forceinline__ void ldsm4t(uint32_t* r, uint32_t a) {
    asm volatile("ldmatrix.sync.aligned.m8n8.x4.trans.shared.b16 {%0,%1,%2,%3}, [%4];"
                 : "=r"(r[0]), "=r"(r[1]), "=r"(r[2]), "=r"(r[3]) : "r"(a));
}
__device__ __forceinline__ void mma_f16(float* d, const uint32_t* a, uint32_t b0, uint32_t b1) {
    asm volatile(
        "mma.sync.aligned.m16n8k16.row.col.f32.f16.f16.f32 "
        "{%0,%1,%2,%3}, {%4,%5,%6,%7}, {%8,%9}, {%0,%1,%2,%3};"
        : "+f"(d[0]), "+f"(d[1]), "+f"(d[2]), "+f"(d[3])
        : "r"(a[0]), "r"(a[1]), "r"(a[2]), "r"(a[3]), "r"(b0), "r"(b1));
}

// ---------------- weight repacks (transpose + fp16 round) ----------------
// Wq pre-scaled by log2(e)/sqrt(HS) so flash works in base-2 (exp -> exp2).
#define QSCALE_ (0.0625f * 1.4426950408889634f)
__global__ void repack_qkvT(const float* __restrict__ Wq, const float* __restrict__ Wk,
                            const float* __restrict__ Wv) {
    int idx = blockIdx.x * blockDim.x + threadIdx.x;     // [0, 1536*512)
    if (idx >= 3 * C_ * C_) return;
    int n = idx / C_, k = idx % C_;
    int part = n / C_;
    int nn = n % C_;
    int h = nn / HS_, d = nn % HS_;
    const float* W = (part == 0) ? Wq : ((part == 1) ? Wk : Wv);
    float scale = (part == 0) ? QSCALE_ : 1.0f;
    g_wqkvT[idx] = __float2half_rn(W[(size_t)h * C_ * HS_ + (size_t)k * HS_ + d] * scale);
}

// merged transpose of Wproj / W1 / W2 -> fp16, one launch.
__global__ void transpose_all(const float* __restrict__ Wproj, const float* __restrict__ W1,
                              const float* __restrict__ W2) {
    __shared__ float t[32][33];
    int bid = blockIdx.x;
    const float* in;
    __half* out;
    int K, N, tt;
    if (bid < 256)       { in = Wproj; out = g_wprojT; K = 512;  N = 512;  tt = bid; }
    else if (bid < 1280) { in = W1;    out = g_w1T;    K = 512;  N = 2048; tt = bid - 256; }
    else                 { in = W2;    out = g_w2T;    K = 2048; N = 512;  tt = bid - 1280; }
    int ntx = N / 32;
    int n0 = (tt % ntx) * 32, k0 = (tt / ntx) * 32;
    int tx = threadIdx.x, ty = threadIdx.y;  // 32x8
#pragma unroll
    for (int i = 0; i < 32; i += 8)
        t[ty + i][tx] = in[(size_t)(k0 + ty + i) * N + n0 + tx];
    __syncthreads();
#pragma unroll
    for (int i = 0; i < 32; i += 8)
        out[(size_t)(n0 + ty + i) * K + k0 + tx] = __float2half_rn(t[tx][ty + i]);
}

// ---------------- LayerNorm: warp per row, shuffle-only, float4 ----------------
__global__ void ln_kernel(const float* __restrict__ x, const float* __restrict__ g,
                          const float* __restrict__ b, __half* __restrict__ out) {
    const int lane = threadIdx.x & 31, wid = threadIdx.x >> 5;
    const int row = blockIdx.x * 8 + wid;
    const float4* xr = (const float4*)(x + (size_t)row * C_);
    float4 v[4];
    float s = 0.f, ss = 0.f;
#pragma unroll
    for (int i = 0; i < 4; i++) {
        v[i] = xr[i * 32 + lane];
        s  += v[i].x + v[i].y + v[i].z + v[i].w;
        ss += v[i].x * v[i].x + v[i].y * v[i].y + v[i].z * v[i].z + v[i].w * v[i].w;
    }
#pragma unroll
    for (int o = 16; o; o >>= 1) {
        s  += __shfl_xor_sync(0xffffffffu, s, o);
        ss += __shfl_xor_sync(0xffffffffu, ss, o);
    }
    float mean = s * (1.0f / C_);
    float var  = ss * (1.0f / C_) - mean * mean;
    float inv  = rsqrtf(var + EPS_);
    const float4* gg4 = (const float4*)g;
    const float4* bb4 = (const float4*)b;
    uint2* orow = (uint2*)(out + (size_t)row * C_);
#pragma unroll
    for (int i = 0; i < 4; i++) {
        float4 gg = gg4[i * 32 + lane], bb = bb4[i * 32 + lane];
        __half2 h0 = __floats2half2_rn((v[i].x - mean) * inv * gg.x + bb.x,
                                       (v[i].y - mean) * inv * gg.y + bb.y);
        __half2 h1 = __floats2half2_rn((v[i].z - mean) * inv * gg.z + bb.z,
                                       (v[i].w - mean) * inv * gg.w + bb.w);
        uint2 o2;
        o2.x = *(uint32_t*)&h0;
        o2.y = *(uint32_t*)&h1;
        orow[i * 32 + lane] = o2;
    }
}

// ---------------- fused flash attention (base-2 online softmax) ---------------------
#define QT_  128
#define KT_  64
#define SRH  264                       // smem row stride in halves (256 + 8 pad)
#define FLASH_SHM ((QT_ + 4 * KT_) * SRH * 2)   // Q + 2 stages of (K+V) = 202752 B

__global__ void __launch_bounds__(256, 1)
flash_kernel(const __half* __restrict__ qkv, const int* __restrict__ mask,
             __half* __restrict__ outh) {
    extern __shared__ __half sh[];
    const uint32_t sb = su32(sh);
    const int tid = threadIdx.x, lane = tid & 31, wid = tid >> 5;
    const int bh = blockIdx.y, b = bh >> 1, h = bh & 1;
    const int q0 = blockIdx.x * QT_;

    const uint32_t suQ = sb;
    const uint32_t suK0 = sb + (uint32_t)(QT_ * SRH * 2);
    const uint32_t stageB = (uint32_t)(2 * KT_ * SRH * 2);

    // ---- stage Q tile (128 x 256 halves) ----
    const int cc16 = tid & 31, rw = tid >> 5;
    {
        const __half* gq = qkv + ((size_t)(b * T_ + q0) + rw) * 1536 + h * HS_ + cc16 * 8;
        uint32_t dq = suQ + (uint32_t)(rw * SRH + cc16 * 8) * 2;
#pragma unroll
        for (int i = 0; i < 16; i++)
            cp16(dq + (uint32_t)(8 * i * SRH) * 2, gq + (size_t)(8 * i) * 1536);
    }
    const __half* gk = qkv + ((size_t)b * T_) * 1536 + C_ + h * HS_ + cc16 * 8;
    const __half* gv = gk + C_;

    // ---- prologue: kv tile 0 ----
    {
        uint32_t dst = suK0 + (uint32_t)(rw * SRH + cc16 * 8) * 2;
#pragma unroll
        for (int i = 0; i < 8; i++) {
            cp16(dst + (uint32_t)(8 * i * SRH) * 2, gk + (size_t)(rw + 8 * i) * 1536);
            cp16(dst + (uint32_t)((KT_ + 8 * i) * SRH) * 2, gv + (size_t)(rw + 8 * i) * 1536);
        }
    }
    asm volatile("cp.async.commit_group;");

    // fragment base addresses
    const uint32_t aAddr = suQ +
        (uint32_t)(((wid * 16 + (lane & 15)) * SRH) * 2 + (lane >> 4) * 16);
    const uint32_t kBase = suK0 +
        (uint32_t)((((lane & 7) + ((lane >> 4) & 1) * 8) * SRH) * 2 + ((lane >> 3) & 1) * 16);
    const uint32_t vBase = suK0 + (uint32_t)(KT_ * SRH * 2) +
        (uint32_t)((((lane & 7) + ((lane >> 3) & 1) * 8) * SRH) * 2 + (lane >> 4) * 16);

    float o[32][4];
#pragma unroll
    for (int i = 0; i < 32; i++)
#pragma unroll
        for (int c = 0; c < 4; c++) o[i][c] = 0.f;
    float m0 = -1e30f, m1 = -1e30f, l0 = 0.f, l1 = 0.f;

    const int qr = q0 + wid * 16 + (lane >> 2);
    const int* mrow0 = mask + ((size_t)b * T_ + qr) * T_;
    const int* mrow1 = mrow0 + 8 * T_;
    const int cq = 2 * (lane & 3);

    const int NJ = T_ / KT_;   // 32
    for (int j = 0; j < NJ; j++) {
        if (j + 1 < NJ) {
            const int kv1 = (j + 1) * KT_;
            uint32_t dst = suK0 + (uint32_t)((j + 1) & 1) * stageB +
                           (uint32_t)(rw * SRH + cc16 * 8) * 2;
#pragma unroll
            for (int i = 0; i < 8; i++) {
                cp16(dst + (uint32_t)(8 * i * SRH) * 2, gk + (size_t)(kv1 + rw + 8 * i) * 1536);
                cp16(dst + (uint32_t)((KT_ + 8 * i) * SRH) * 2,
                     gv + (size_t)(kv1 + rw + 8 * i) * 1536);
            }
        }
        asm volatile("cp.async.commit_group;");
        asm volatile("cp.async.wait_group 1;");    // tile j (and Q) resident
        __syncthreads();
        const uint32_t soff = (uint32_t)(j & 1) * stageB;

        // ---- S = Q K^T  (16 x 64 per warp) ----
        float s[8][4];
#pragma unroll
        for (int nt = 0; nt < 8; nt++)
#pragma unroll
            for (int c = 0; c < 4; c++) s[nt][c] = 0.f;
#pragma unroll
        for (int ks = 0; ks < 16; ks++) {
            uint32_t aR[4];
            ldsm4(aR, aAddr + ks * 32);
#pragma unroll
            for (int ng = 0; ng < 4; ng++) {
                uint32_t bR[4];
                ldsm4(bR, kBase + soff + (uint32_t)(16 * ng * SRH) * 2 + ks * 32);
                mma_f16(s[2 * ng],     aR, bR[0], bR[1]);
                mma_f16(s[2 * ng + 1], aR, bR[2], bR[3]);
            }
        }

        // ---- mask + online softmax (base-2) ----
        const int kv0 = j * KT_;
        float mx0 = -1e30f, mx1 = -1e30f;
#pragma unroll
        for (int nt = 0; nt < 8; nt++) {
            int col = kv0 + nt * 8 + cq;
            int2 ma = *(const int2*)(mrow0 + col);
            int2 mb = *(const int2*)(mrow1 + col);
            if (ma.x == 0) s[nt][0] = -1e30f;
            if (ma.y == 0) s[nt][1] = -1e30f;
            if (mb.x == 0) s[nt][2] = -1e30f;
            if (mb.y == 0) s[nt][3] = -1e30f;
            mx0 = fmaxf(mx0, fmaxf(s[nt][0], s[nt][1]));
            mx1 = fmaxf(mx1, fmaxf(s[nt][2], s[nt][3]));
        }
        mx0 = fmaxf(mx0, __shfl_xor_sync(0xffffffffu, mx0, 1));
        mx0 = fmaxf(mx0, __shfl_xor_sync(0xffffffffu, mx0, 2));
        mx1 = fmaxf(mx1, __shfl_xor_sync(0xffffffffu, mx1, 1));
        mx1 = fmaxf(mx1, __shfl_xor_sync(0xffffffffu, mx1, 2));
        float mn0 = fmaxf(m0, mx0), mn1 = fmaxf(m1, mx1);
        float al0 = exp2f(m0 - mn0), al1 = exp2f(m1 - mn1);   // ==1.0f when no new max
        m0 = mn0; m1 = mn1;

        float rs0 = 0.f, rs1 = 0.f;
        uint32_t pH[8][2];
#pragma unroll
        for (int nt = 0; nt < 8; nt++) {
            __half2 e01 = h2exp2(__floats2half2_rn(s[nt][0] - mn0, s[nt][1] - mn0));
            __half2 e23 = h2exp2(__floats2half2_rn(s[nt][2] - mn1, s[nt][3] - mn1));
            pH[nt][0] = *(uint32_t*)&e01;
            pH[nt][1] = *(uint32_t*)&e23;
            float2 f01 = __half22float2(e01), f23 = __half22float2(e23);
            rs0 += f01.x + f01.y;
            rs1 += f23.x + f23.y;
        }
        rs0 += __shfl_xor_sync(0xffffffffu, rs0, 1);
        rs0 += __shfl_xor_sync(0xffffffffu, rs0, 2);
        rs1 += __shfl_xor_sync(0xffffffffu, rs1, 1);
        rs1 += __shfl_xor_sync(0xffffffffu, rs1, 2);
        l0 = l0 * al0 + rs0;
        l1 = l1 * al1 + rs1;
        if (__any_sync(0xffffffffu, (al0 != 1.f) | (al1 != 1.f))) {
#pragma unroll
            for (int nt = 0; nt < 32; nt++) {
                o[nt][0] *= al0; o[nt][1] *= al0;
                o[nt][2] *= al1; o[nt][3] *= al1;
            }
        }

        // ---- O += P V ----
#pragma unroll
        for (int ks = 0; ks < 4; ks++) {
            uint32_t aF[4] = { pH[2 * ks][0], pH[2 * ks][1],
                               pH[2 * ks + 1][0], pH[2 * ks + 1][1] };
#pragma unroll
            for (int ng = 0; ng < 16; ng++) {
                uint32_t vR[4];
                ldsm4t(vR, vBase + soff + (uint32_t)(16 * ks * SRH + 16 * ng) * 2);
                mma_f16(o[2 * ng],     aF, vR[0], vR[1]);
                mma_f16(o[2 * ng + 1], aF, vR[2], vR[3]);
            }
        }
        __syncthreads();   // all warps done with buffer before next-iter overwrite
    }

    // ---- finalize + store (concat-head layout) ----
    float i0 = 1.f / l0, i1 = 1.f / l1;
    __half* orow0 = outh + ((size_t)(b * T_) + qr) * C_ + h * HS_;
    __half* orow1 = orow0 + 8 * C_;
#pragma unroll
    for (int nt = 0; nt < 32; nt++) {
        int col = nt * 8 + cq;
        __half2 w0 = __floats2half2_rn(o[nt][0] * i0, o[nt][1] * i0);
        __half2 w1 = __floats2half2_rn(o[nt][2] * i1, o[nt][3] * i1);
        *(__half2*)(orow0 + col) = w0;
        *(__half2*)(orow1 + col) = w1;
    }
}

// ---------------- mma.sync fp16 NT GEMM: 128x128 tile, K=64/stage, 2 stages --------
// 256 thr / 8 warps, warp tile 32x64. Per iter: 4 k-steps = 64 mmas/warp between
// barriers (4x round 8). One __syncthreads per iter. 2 CTAs/SM (73.7 KB smem each).
#define SROWB  144                  // 128 B data + 16 B pad per row
#define TILEB  (128 * SROWB)        // 18432 B
#define STAGEB (2 * TILEB)          // 36864 B (A + B tile)
#define SHMB   (2 * STAGEB)         // 73728 B

template <int MODE>
__global__ void __launch_bounds__(256, 2)
mma_gemm(const __half* __restrict__ A, const __half* __restrict__ Bm, void* __restrict__ Cout,
         const float* __restrict__ bias, const float* __restrict__ res,
         int K, int lda, int ldb, int ldc) {
    extern __shared__ char smraw[];
    const uint32_t sbase = su32(smraw);
    const int tid = threadIdx.x, lane = tid & 31, wid = tid >> 5;
    const int wm = wid >> 1, wn = wid & 1;   // 4 x 2 warp grid

    const int m0 = blockIdx.y * 128, n0 = blockIdx.x * 128;

    float acc[2][8][4];
#pragma unroll
    for (int i = 0; i < 2; i++)
#pragma unroll
        for (int j = 0; j < 8; j++)
#pragma unroll
            for (int c = 0; c < 4; c++) acc[i][j][c] = 0.f;

    // gmem->smem: thread owns 16B chunk c8 of rows r0 + 32t (t<4), per matrix
    const int c8 = tid & 7, r0 = tid >> 3;
    const uint32_t dA0 = sbase + (uint32_t)(r0 * SROWB + c8 * 16);
    const uint32_t dB0 = dA0 + TILEB;
    const __half* gA0 = A  + (size_t)(m0 + r0) * lda + c8 * 8;
    const __half* gB0 = Bm + (size_t)(n0 + r0) * ldb + c8 * 8;
    const int nk = K >> 6;

    const uint32_t aF0 = sbase + (uint32_t)((wm * 32 + (lane & 15)) * SROWB + (lane >> 4) * 16);
    const uint32_t bF0 = sbase + TILEB +
        (uint32_t)((wn * 64 + (lane & 7) + ((lane >> 4) & 1) * 8) * SROWB + ((lane >> 3) & 1) * 16);

    // prologue: stage 0
#pragma unroll
    for (int t = 0; t < 4; t++) {
        cp16(dA0 + (uint32_t)(32 * t * SROWB), gA0 + (size_t)(32 * t) * lda);
        cp16(dB0 + (uint32_t)(32 * t * SROWB), gB0 + (size_t)(32 * t) * ldb);
    }
    asm volatile("cp.async.commit_group;");

    for (int j = 0; j < nk; j++) {
        asm volatile("cp.async.wait_group 0;");   // stage j landed
        __syncthreads();                          // all warps done with buf (j+1)&1

        if (j + 1 < nk) {
            const uint32_t soff = (uint32_t)((j + 1) & 1) * STAGEB;
            const __half* ga = gA0 + (j + 1) * 64;
            const __half* gb = gB0 + (j + 1) * 64;
#pragma unroll
            for (int t = 0; t < 4; t++) {
                cp16(dA0 + soff + (uint32_t)(32 * t * SROWB), ga + (size_t)(32 * t) * lda);
                cp16(dB0 + soff + (uint32_t)(32 * t * SROWB), gb + (size_t)(32 * t) * ldb);
            }
            asm volatile("cp.async.commit_group;");
        }

        const uint32_t sa = aF0 + (uint32_t)(j & 1) * STAGEB;
        const uint32_t sb = bF0 + (uint32_t)(j & 1) * STAGEB;
#pragma unroll
        for (int ks = 0; ks < 4; ks++) {
            uint32_t aR[2][4], bR[4][4];
#pragma unroll
            for (int mt = 0; mt < 2; mt++)
                ldsm4(aR[mt], sa + (uint32_t)(mt * 16 * SROWB + ks * 32));
#pragma unroll
            for (int np = 0; np < 4; np++)
                ldsm4(bR[np], sb + (uint32_t)(np * 16 * SROWB + ks * 32));
#pragma unroll
            for (int mt = 0; mt < 2; mt++)
#pragma unroll
                for (int nt = 0; nt < 8; nt++)
                    mma_f16(acc[mt][nt], aR[mt],
                            bR[nt >> 1][(nt & 1) * 2], bR[nt >> 1][(nt & 1) * 2 + 1]);
        }
    }

    const int r = lane >> 2, cq = 2 * (lane & 3);
#pragma unroll
    for (int mt = 0; mt < 2; mt++) {
        const int row0 = m0 + wm * 32 + mt * 16 + r;
#pragma unroll
        for (int nt = 0; nt < 8; nt++) {
            const int col = n0 + wn * 64 + nt * 8 + cq;
            float v0 = acc[mt][nt][0], v1 = acc[mt][nt][1];
            float v2 = acc[mt][nt][2], v3 = acc[mt][nt][3];
            if (MODE == 1) {
                float* Cm = (float*)Cout;
                float b0 = bias[col], b1 = bias[col + 1];
                const float* r0p = res + (size_t)row0 * ldc + col;
                const float* r1p = res + (size_t)(row0 + 8) * ldc + col;
                float2 o0, o1;
                o0.x = v0 + b0 + r0p[0]; o0.y = v1 + b1 + r0p[1];
                o1.x = v2 + b0 + r1p[0]; o1.y = v3 + b1 + r1p[1];
                *(float2*)(Cm + (size_t)row0 * ldc + col) = o0;
                *(float2*)(Cm + (size_t)(row0 + 8) * ldc + col) = o1;
            } else {
                __half* Cm = (__half*)Cout;
                __half2 h0, h1;
                if (MODE == 2) {
                    float b0 = bias[col], b1 = bias[col + 1];
                    h0 = __floats2half2_rn(fmaxf(v0 + b0, 0.f), fmaxf(v1 + b1, 0.f));
                    h1 = __floats2half2_rn(fmaxf(v2 + b0, 0.f), fmaxf(v3 + b1, 0.f));
                } else {
                    h0 = __floats2half2_rn(v0, v1);
                    h1 = __floats2half2_rn(v2, v3);
                }
                *(__half2*)(Cm + (size_t)row0 * ldc + col) = h0;
                *(__half2*)(Cm + (size_t)(row0 + 8) * ldc + col) = h1;
            }
        }
    }
}

// ---------------- host launcher ----------------
extern "C" void kernel_launch(void* const* d_in, const int* in_sizes, int n_in,
                              void* d_out, int out_size) {
    const float* x     = (const float*)d_in[0];
    const int*   smask = (const int*)d_in[1];
    const float* Wq    = (const float*)d_in[2];
    const float* Wk    = (const float*)d_in[3];
    const float* Wv    = (const float*)d_in[4];
    const float* Wproj = (const float*)d_in[5];
    const float* bproj = (const float*)d_in[6];
    const float* W1    = (const float*)d_in[7];
    const float* b1    = (const float*)d_in[8];
    const float* W2    = (const float*)d_in[9];
    const float* b2    = (const float*)d_in[10];
    const float* g1    = (const float*)d_in[11];
    const float* be1   = (const float*)d_in[12];
    const float* g2    = (const float*)d_in[13];
    const float* be2   = (const float*)d_in[14];
    float* out = (float*)d_out;

    __half *pH, *pQKV, *pF1, *pWqkvT, *pWprojT, *pW1T, *pW2T;
    float* pX1;
    cudaGetSymbolAddress((void**)&pH,      g_h);
    cudaGetSymbolAddress((void**)&pQKV,    g_qkv);
    cudaGetSymbolAddress((void**)&pX1,     g_x1);
    cudaGetSymbolAddress((void**)&pF1,     g_f1);
    cudaGetSymbolAddress((void**)&pWqkvT,  g_wqkvT);
    cudaGetSymbolAddress((void**)&pWprojT, g_wprojT);
    cudaGetSymbolAddress((void**)&pW1T,    g_w1T);
    cudaGetSymbolAddress((void**)&pW2T,    g_w2T);

    cudaFuncSetAttribute(mma_gemm<1>, cudaFuncAttributeMaxDynamicSharedMemorySize, SHMB);
    cudaFuncSetAttribute(mma_gemm<2>, cudaFuncAttributeMaxDynamicSharedMemorySize, SHMB);
    cudaFuncSetAttribute(mma_gemm<3>, cudaFuncAttributeMaxDynamicSharedMemorySize, SHMB);
    cudaFuncSetAttribute(flash_kernel, cudaFuncAttributeMaxDynamicSharedMemorySize, FLASH_SHM);
    dim3 blk(256);

    // weight repacks (rounded to fp16; Wq pre-scaled log2e/16)
    repack_qkvT<<<(3 * C_ * C_ + 255) / 256, 256>>>(Wq, Wk, Wv);
    transpose_all<<<2304, dim3(32, 8)>>>(Wproj, W1, W2);

    // LN1
    ln_kernel<<<BT_ / 8, 256>>>(x, g1, be1, pH);

    // QKV fused: [BT,512] x [1536,512]^T -> [BT,1536]
    mma_gemm<3><<<dim3(12, 128, 1), blk, SHMB>>>(pH, pWqkvT, pQKV, nullptr, nullptr,
        C_, C_, C_, 3 * C_);

    // fused flash attention -> pH (concat-head fp16)
    flash_kernel<<<dim3(T_ / QT_, B_ * H_), 256, FLASH_SHM>>>(pQKV, smask, pH);

    // x1 = x + o @ Wproj + bproj
    mma_gemm<1><<<dim3(4, 128, 1), blk, SHMB>>>(pH, pWprojT, pX1, bproj, x,
        C_, C_, C_, C_);

    // LN2
    ln_kernel<<<BT_ / 8, 256>>>(pX1, g2, be2, pH);

    // f1 = relu(h2 @ W1 + b1)
    mma_gemm<2><<<dim3(16, 128, 1), blk, SHMB>>>(pH, pW1T, pF1, b1, nullptr,
        C_, C_, C_, 4 * C_);

    // out = x1 + f1 @ W2 + b2
    mma_gemm<1><<<dim3(4, 128, 1), blk, SHMB>>>(pF1, pW2T, out, b2, pX1,
        4 * C_, 4 * C_, 4 * C_, C_);
}